// round 1
// baseline (speedup 1.0000x reference)
#include <cuda_runtime.h>

#define N_NODES 50000
#define N_EDGES 800000
#define HID     128
#define N_GRAPHS 32
#define LN_EPS  1e-5f
#define SW_STRIDE 132   // padded W smem row stride (floats): lane stride 132 %32 = 4 -> conflict-free LDS.128

typedef unsigned long long ull;

// ---------------- scratch (device globals; no allocations allowed) ----------------
__device__ float g_h[N_NODES * HID];
__device__ float g_t[N_NODES * HID];
__device__ float g_agg[N_NODES * HID];
__device__ float g_dis[N_NODES];
__device__ int   g_deg[N_NODES];
__device__ int   g_row[N_EDGES];
__device__ int   g_col[N_EDGES];
__device__ int   g_batch[N_NODES];
__device__ float g_sums[N_GRAPHS];
__device__ int   g_cnts[N_GRAPHS];
__device__ int   g_flag64;

// ---------------- helpers: packed f32x2 FMA (Blackwell) ----------------
__device__ __forceinline__ ull pk(float lo, float hi) {
    ull r; asm("mov.b64 %0, {%1,%2};" : "=l"(r) : "f"(lo), "f"(hi)); return r;
}
__device__ __forceinline__ void fma2(ull& d, ull a, ull b) {
    asm("fma.rn.f32x2 %0, %1, %2, %0;" : "+l"(d) : "l"(a), "l"(b));
}
__device__ __forceinline__ float2 upk(ull v) {
    float2 f; asm("mov.b64 {%0,%1}, %2;" : "=f"(f.x), "=f"(f.y) : "l"(v)); return f;
}
__device__ __forceinline__ float comp(const float4& v, int i) {
    return i == 0 ? v.x : (i == 1 ? v.y : (i == 2 ? v.z : v.w));
}

// ---------------- dtype detection: int64 indices have zero high words ----------------
__global__ void k_detect(const unsigned int* ei) {
    if (threadIdx.x == 0) {
        int is64 = 1;
        for (int i = 1; i < 256; i += 2)
            if (ei[i] != 0u) { is64 = 0; break; }
        g_flag64 = is64;
    }
}

// convert indices to int32 scratch; init deg=1 (self loop); zero graph accumulators
__global__ void k_convert(const void* ei, const void* batch) {
    int i = blockIdx.x * blockDim.x + threadIdx.x;
    int f64 = g_flag64;
    if (i < N_EDGES) {
        if (f64) {
            const long long* p = (const long long*)ei;
            g_row[i] = (int)p[i];
            g_col[i] = (int)p[N_EDGES + i];
        } else {
            const int* p = (const int*)ei;
            g_row[i] = p[i];
            g_col[i] = p[N_EDGES + i];
        }
    }
    if (i < N_NODES) {
        int b = f64 ? (int)((const long long*)batch)[i] : ((const int*)batch)[i];
        g_batch[i] = b;
        g_deg[i] = 1;
    }
    if (i < N_GRAPHS) { g_sums[i] = 0.f; g_cnts[i] = 0; }
}

__global__ void k_deg() {
    int e = blockIdx.x * blockDim.x + threadIdx.x;
    if (e < N_EDGES) atomicAdd(&g_deg[g_col[e]], 1);
}

__global__ void k_dis() {
    int v = blockIdx.x * blockDim.x + threadIdx.x;
    if (v < N_NODES) g_dis[v] = rsqrtf((float)g_deg[v]);
}

// ---------------- GEMM: C[n][o] = sum_k A[n][k]*W[o][k] (+bias) ----------------
// mode 0: A = x (param), C = g_h, add bias
// mode 1: A = g_h,        C = g_t, also g_agg = dis^2 * t (self-loop init)
__global__ void __launch_bounds__(256) k_gemm(const float* __restrict__ A,
                                              const float* __restrict__ W,
                                              const float* __restrict__ bias,
                                              int mode) {
    extern __shared__ float sm[];
    float* sw = sm;                       // 128 x SW_STRIDE
    float* sa = sm + 128 * SW_STRIDE;     // 64 x 128

    const float* Ap = mode ? g_h : A;
    float* C  = mode ? g_t : g_h;

    int tid  = threadIdx.x;
    int row0 = blockIdx.x * 64;

    // stage W (128x128) into padded smem
    #pragma unroll
    for (int i = 0; i < 16; i++) {
        int f = tid + i * 256;            // float4 index, 4096 total
        int o = f >> 5, k4 = f & 31;
        float4 v = ((const float4*)W)[f];
        *(float4*)(sw + o * SW_STRIDE + k4 * 4) = v;
    }
    // stage A tile (64x128)
    #pragma unroll
    for (int i = 0; i < 8; i++) {
        int f = tid + i * 256;            // 2048 float4
        int r = f >> 5, k4 = f & 31;
        int gr = row0 + r;
        float4 v = (gr < N_NODES) ? ((const float4*)Ap)[gr * 32 + k4]
                                  : make_float4(0.f, 0.f, 0.f, 0.f);
        *(float4*)(sa + r * 128 + k4 * 4) = v;
    }
    __syncthreads();

    int lane = tid & 31, warp = tid >> 5;
    int r0 = warp * 8;                    // 8 rows per warp, 4 cols per lane

    ull acc[4][4];
    #pragma unroll
    for (int a = 0; a < 4; a++)
        #pragma unroll
        for (int b = 0; b < 4; b++) acc[a][b] = 0ULL;

    #pragma unroll 4
    for (int k4 = 0; k4 < 32; k4++) {
        int k = k4 * 4;
        float4 av[8];
        #pragma unroll
        for (int r = 0; r < 8; r++) av[r] = *(const float4*)(sa + (r0 + r) * 128 + k);
        float4 wv[4];
        #pragma unroll
        for (int c = 0; c < 4; c++) wv[c] = *(const float4*)(sw + (lane + 32 * c) * SW_STRIDE + k);
        #pragma unroll
        for (int kk = 0; kk < 4; kk++) {
            ull a2[4], w2[4];
            #pragma unroll
            for (int rp = 0; rp < 4; rp++)
                a2[rp] = pk(comp(av[2 * rp], kk), comp(av[2 * rp + 1], kk));
            #pragma unroll
            for (int c = 0; c < 4; c++) { float w = comp(wv[c], kk); w2[c] = pk(w, w); }
            #pragma unroll
            for (int rp = 0; rp < 4; rp++)
                #pragma unroll
                for (int c = 0; c < 4; c++) fma2(acc[rp][c], a2[rp], w2[c]);
        }
    }

    // epilogue
    #pragma unroll
    for (int rp = 0; rp < 4; rp++) {
        int gr0 = row0 + r0 + 2 * rp;
        #pragma unroll
        for (int c = 0; c < 4; c++) {
            float2 v = upk(acc[rp][c]);
            int col = lane + 32 * c;
            if (mode == 0) {
                float bb = bias[col];
                if (gr0 < N_NODES)     C[gr0 * HID + col]       = v.x + bb;
                if (gr0 + 1 < N_NODES) C[(gr0 + 1) * HID + col] = v.y + bb;
            } else {
                if (gr0 < N_NODES) {
                    float d = g_dis[gr0];
                    C[gr0 * HID + col] = v.x;
                    g_agg[gr0 * HID + col] = d * d * v.x;
                }
                if (gr0 + 1 < N_NODES) {
                    float d = g_dis[gr0 + 1];
                    C[(gr0 + 1) * HID + col] = v.y;
                    g_agg[(gr0 + 1) * HID + col] = d * d * v.y;
                }
            }
        }
    }
}

// ---------------- edge scatter: agg[col] += norm * t[row] (warp per edge) ----------------
__global__ void k_scatter() {
    int wid = (blockIdx.x * blockDim.x + threadIdx.x) >> 5;
    if (wid >= N_EDGES) return;
    int lane = threadIdx.x & 31;
    int r = g_row[wid], c = g_col[wid];
    float nrm = g_dis[r] * g_dis[c];
    float4 v = *(const float4*)(g_t + r * HID + lane * 4);
    float* dst = g_agg + c * HID + lane * 4;
    asm volatile("red.global.add.v4.f32 [%0], {%1,%2,%3,%4};"
                 :: "l"(dst), "f"(v.x * nrm), "f"(v.y * nrm), "f"(v.z * nrm), "f"(v.w * nrm)
                 : "memory");
}

// ---------------- h = LayerNorm(h + relu(agg + b)) (warp per node) ----------------
__global__ void k_ln(const float* __restrict__ b, const float* __restrict__ gamma,
                     const float* __restrict__ beta) {
    int v = (blockIdx.x * blockDim.x + threadIdx.x) >> 5;
    if (v >= N_NODES) return;
    int lane = threadIdx.x & 31;
    float4 hv = *(const float4*)(g_h + v * HID + lane * 4);
    float4 av = *(const float4*)(g_agg + v * HID + lane * 4);
    float4 bv = *(const float4*)(b + lane * 4);
    float x0 = hv.x + fmaxf(av.x + bv.x, 0.f);
    float x1 = hv.y + fmaxf(av.y + bv.y, 0.f);
    float x2 = hv.z + fmaxf(av.z + bv.z, 0.f);
    float x3 = hv.w + fmaxf(av.w + bv.w, 0.f);
    float s = x0 + x1 + x2 + x3;
    #pragma unroll
    for (int off = 16; off > 0; off >>= 1) s += __shfl_xor_sync(0xffffffffu, s, off);
    float mu = s * (1.f / 128.f);
    float d0 = x0 - mu, d1 = x1 - mu, d2 = x2 - mu, d3 = x3 - mu;
    float q = d0 * d0 + d1 * d1 + d2 * d2 + d3 * d3;
    #pragma unroll
    for (int off = 16; off > 0; off >>= 1) q += __shfl_xor_sync(0xffffffffu, q, off);
    float rs = rsqrtf(q * (1.f / 128.f) + LN_EPS);
    float4 gv = *(const float4*)(gamma + lane * 4);
    float4 be = *(const float4*)(beta + lane * 4);
    float4 o;
    o.x = d0 * rs * gv.x + be.x;
    o.y = d1 * rs * gv.y + be.y;
    o.z = d2 * rs * gv.z + be.z;
    o.w = d3 * rs * gv.w + be.w;
    *(float4*)(g_h + v * HID + lane * 4) = o;
}

// ---------------- output head + mean pool (batch is sorted -> block-local reduce) -------
__global__ void k_pool(const float* __restrict__ Wout) {
    __shared__ float swv[HID];
    __shared__ float ssum[N_GRAPHS];
    __shared__ int   scnt[N_GRAPHS];
    int tid = threadIdx.x;
    if (tid < HID) swv[tid] = Wout[tid];
    if (tid < N_GRAPHS) { ssum[tid] = 0.f; scnt[tid] = 0; }
    __syncthreads();
    int v = (blockIdx.x * blockDim.x + tid) >> 5;
    int lane = tid & 31;
    if (v < N_NODES) {
        float4 hv = *(const float4*)(g_h + v * HID + lane * 4);
        float4 wv = *(const float4*)(swv + lane * 4);
        float s = hv.x * wv.x + hv.y * wv.y + hv.z * wv.z + hv.w * wv.w;
        #pragma unroll
        for (int off = 16; off > 0; off >>= 1) s += __shfl_xor_sync(0xffffffffu, s, off);
        if (lane == 0) {
            int b = g_batch[v];
            atomicAdd(&ssum[b], s);
            atomicAdd(&scnt[b], 1);
        }
    }
    __syncthreads();
    if (tid < N_GRAPHS && scnt[tid] > 0) {
        atomicAdd(&g_sums[tid], ssum[tid]);
        atomicAdd(&g_cnts[tid], scnt[tid]);
    }
}

__global__ void k_out(float* out) {
    int g = threadIdx.x;
    if (g < N_GRAPHS) out[g] = g_sums[g] / fmaxf((float)g_cnts[g], 1.f);
}

// ---------------- launch ----------------
extern "C" void kernel_launch(void* const* d_in, const int* in_sizes, int n_in,
                              void* d_out, int out_size) {
    const float* x        = (const float*)d_in[0];
    const void*  ei       = d_in[1];
    const void*  batch    = d_in[2];
    const float* W_emb    = (const float*)d_in[3];
    const float* b_emb    = (const float*)d_in[4];
    const float* W_layers = (const float*)d_in[5];
    const float* b_layers = (const float*)d_in[6];
    const float* ln_gamma = (const float*)d_in[7];
    const float* ln_beta  = (const float*)d_in[8];
    const float* W_out    = (const float*)d_in[9];
    float* out = (float*)d_out;

    const size_t GEMM_SMEM = (128 * SW_STRIDE + 64 * 128) * sizeof(float);
    cudaFuncSetAttribute(k_gemm, cudaFuncAttributeMaxDynamicSharedMemorySize, (int)GEMM_SMEM);

    k_detect<<<1, 32>>>((const unsigned int*)ei);
    k_convert<<<(N_EDGES + 255) / 256, 256>>>(ei, batch);
    k_deg<<<(N_EDGES + 255) / 256, 256>>>();
    k_dis<<<(N_NODES + 255) / 256, 256>>>();

    int gemm_blocks = (N_NODES + 63) / 64;
    k_gemm<<<gemm_blocks, 256, GEMM_SMEM>>>(x, W_emb, b_emb, 0);

    int scat_blocks = (N_EDGES * 32 + 255) / 256;
    int ln_blocks   = (N_NODES * 32 + 511) / 512;
    for (int i = 0; i < 4; i++) {
        k_gemm<<<gemm_blocks, 256, GEMM_SMEM>>>(nullptr, W_layers + i * HID * HID, nullptr, 1);
        k_scatter<<<scat_blocks, 256>>>();
        k_ln<<<ln_blocks, 512>>>(b_layers + i * HID, ln_gamma + i * HID, ln_beta + i * HID);
    }

    k_pool<<<(N_NODES * 32 + 511) / 512, 512>>>(W_out);
    k_out<<<1, 32>>>(out);
}

// round 2
// speedup vs baseline: 1.3643x; 1.3643x over previous
#include <cuda_runtime.h>

#define N_NODES 50000
#define N_EDGES 800000
#define HID     128
#define N_GRAPHS 32
#define LN_EPS  1e-5f

typedef unsigned long long ull;

// ---------------- scratch (device globals; no allocations allowed) ----------------
__device__ float g_h[N_NODES * HID];
__device__ float g_t[N_NODES * HID];       // t' = dis[v] * (h W^T)
__device__ float g_Wt[5 * HID * HID];      // transposed weights Wt[k][o]
__device__ float g_dis[N_NODES];
__device__ int   g_edeg[N_NODES];          // edge-only in-degree (self-loop excluded)
__device__ int   g_off[N_NODES + 1];
__device__ int   g_cursor[N_NODES];
__device__ int   g_csr[N_EDGES];           // source rows grouped by target col
__device__ int   g_row[N_EDGES];
__device__ int   g_col[N_EDGES];
__device__ int   g_batch[N_NODES];
__device__ float g_sums[N_GRAPHS];
__device__ int   g_cnts[N_GRAPHS];
__device__ int   g_flag64;

// ---------------- packed f32x2 FMA helpers (Blackwell FFMA2) ----------------
__device__ __forceinline__ ull pk(float lo, float hi) {
    ull r; asm("mov.b64 %0, {%1,%2};" : "=l"(r) : "f"(lo), "f"(hi)); return r;
}
__device__ __forceinline__ void fma2(ull& d, ull a, ull b) {
    asm("fma.rn.f32x2 %0, %1, %2, %0;" : "+l"(d) : "l"(a), "l"(b));
}
__device__ __forceinline__ float2 upk(ull v) {
    float2 f; asm("mov.b64 {%0,%1}, %2;" : "=f"(f.x), "=f"(f.y) : "l"(v)); return f;
}
__device__ __forceinline__ float comp(const float4& v, int i) {
    return i == 0 ? v.x : (i == 1 ? v.y : (i == 2 ? v.z : v.w));
}

// ---------------- dtype detection: int64 indices have zero high words ----------------
__global__ void k_detect(const unsigned int* ei) {
    if (threadIdx.x == 0) {
        int is64 = 1;
        for (int i = 1; i < 256; i += 2)
            if (ei[i] != 0u) { is64 = 0; break; }
        g_flag64 = is64;
    }
}

// convert indices; zero edeg; load batch; zero pool accumulators
__global__ void k_convert(const void* ei, const void* batch) {
    int i = blockIdx.x * blockDim.x + threadIdx.x;
    int f64 = g_flag64;
    if (i < N_EDGES) {
        if (f64) {
            const long long* p = (const long long*)ei;
            g_row[i] = (int)p[i];
            g_col[i] = (int)p[N_EDGES + i];
        } else {
            const int* p = (const int*)ei;
            g_row[i] = p[i];
            g_col[i] = p[N_EDGES + i];
        }
    }
    if (i < N_NODES) {
        int b = f64 ? (int)((const long long*)batch)[i] : ((const int*)batch)[i];
        g_batch[i] = b;
        g_edeg[i] = 0;
    }
    if (i < N_GRAPHS) { g_sums[i] = 0.f; g_cnts[i] = 0; }
}

__global__ void k_deg() {
    int e = blockIdx.x * blockDim.x + threadIdx.x;
    if (e < N_EDGES) atomicAdd(&g_edeg[g_col[e]], 1);
}

// single-block exclusive scan -> CSR offsets + cursors + dis
__global__ void __launch_bounds__(1024) k_scan() {
    __shared__ int sp[1024];
    int tid = threadIdx.x;
    const int CH = (N_NODES + 1023) / 1024;     // 49
    int base = tid * CH;
    int s = 0;
    for (int j = 0; j < CH; j++) { int v = base + j; if (v < N_NODES) s += g_edeg[v]; }
    sp[tid] = s; __syncthreads();
    for (int off = 1; off < 1024; off <<= 1) {
        int v = (tid >= off) ? sp[tid - off] : 0;
        __syncthreads();
        sp[tid] += v;
        __syncthreads();
    }
    int run = sp[tid] - s;                       // exclusive prefix
    for (int j = 0; j < CH; j++) {
        int v = base + j;
        if (v < N_NODES) {
            g_off[v] = run;
            g_cursor[v] = run;
            int d = g_edeg[v];
            g_dis[v] = rsqrtf((float)(d + 1));   // +1 self loop
            run += d;
        }
    }
    if (tid == 1023) g_off[N_NODES] = run;
}

__global__ void k_fill() {
    int e = blockIdx.x * blockDim.x + threadIdx.x;
    if (e < N_EDGES) {
        int c = g_col[e];
        int pos = atomicAdd(&g_cursor[c], 1);
        g_csr[pos] = g_row[e];
    }
}

// transpose all 5 weight matrices: g_Wt[w][k][o] = W[w][o][k]
__global__ void k_transpose(const float* __restrict__ W_emb, const float* __restrict__ W_layers) {
    int i = blockIdx.x * blockDim.x + threadIdx.x;
    if (i >= 5 * HID * HID) return;
    int w = i >> 14, r = i & 16383;
    int o = r >> 7, k = r & 127;
    float v = (w == 0) ? W_emb[r] : W_layers[(w - 1) * 16384 + r];
    g_Wt[w * 16384 + k * HID + o] = v;
}

// ---------------- GEMM: out[n][o] = sum_k A[n][k] * Wt[k][o]  ----------------
// Block: 64 rows x 128 cols. 256 threads; warp w handles 64 rows x cols [16w,16w+16).
// W reads from smem are lane-uniform broadcasts -> crossbar cheap; FMA2-bound.
// mode 0: out = g_h = A Wt + bias.   mode 1: out = g_t = dis[row] * (A Wt).
__global__ void __launch_bounds__(256) k_gemm(const float* __restrict__ A,
                                              const float* __restrict__ Wt,
                                              const float* __restrict__ bias,
                                              int mode) {
    extern __shared__ float sm[];
    float* sw = sm;                 // 128 x 132  (sw[k*132+o] = Wt[k][o])
    float* sa = sm + 128 * 132;     // 64 x 132

    int tid = threadIdx.x;
    int row0 = blockIdx.x * 64;

    // stage Wt (coalesced load, conflict-free store)
    #pragma unroll
    for (int i = 0; i < 16; i++) {
        int f = tid + i * 256;      // float4 index over 128x128
        int k = f >> 5, o4 = f & 31;
        float4 v = ((const float4*)Wt)[f];
        *(float4*)(sw + k * 132 + o4 * 4) = v;
    }
    // stage A tile 64x128
    #pragma unroll
    for (int i = 0; i < 8; i++) {
        int f = tid + i * 256;      // 2048 float4
        int r = f >> 5, k4 = f & 31;
        int gr = row0 + r;
        float4 v = (gr < N_NODES) ? ((const float4*)A)[gr * 32 + k4]
                                  : make_float4(0.f, 0.f, 0.f, 0.f);
        *(float4*)(sa + r * 132 + k4 * 4) = v;
    }
    __syncthreads();

    int lane = tid & 31, warp = tid >> 5;
    int c0 = warp * 16;

    ull acc0[8], acc1[8];
    #pragma unroll
    for (int p = 0; p < 8; p++) { acc0[p] = 0ULL; acc1[p] = 0ULL; }

    #pragma unroll 2
    for (int k4 = 0; k4 < 32; k4++) {
        float4 aA = *(const float4*)(sa + lane * 132 + k4 * 4);
        float4 aB = *(const float4*)(sa + (lane + 32) * 132 + k4 * 4);
        #pragma unroll
        for (int kk = 0; kk < 4; kk++) {
            const float* wr = sw + (k4 * 4 + kk) * 132 + c0;
            float4 w0 = *(const float4*)(wr);
            float4 w1 = *(const float4*)(wr + 4);
            float4 w2 = *(const float4*)(wr + 8);
            float4 w3 = *(const float4*)(wr + 12);
            float avA = comp(aA, kk), avB = comp(aB, kk);
            ull a0 = pk(avA, avA), a1 = pk(avB, avB);
            ull wp0 = pk(w0.x, w0.y), wp1 = pk(w0.z, w0.w);
            ull wp2 = pk(w1.x, w1.y), wp3 = pk(w1.z, w1.w);
            ull wp4 = pk(w2.x, w2.y), wp5 = pk(w2.z, w2.w);
            ull wp6 = pk(w3.x, w3.y), wp7 = pk(w3.z, w3.w);
            fma2(acc0[0], a0, wp0); fma2(acc1[0], a1, wp0);
            fma2(acc0[1], a0, wp1); fma2(acc1[1], a1, wp1);
            fma2(acc0[2], a0, wp2); fma2(acc1[2], a1, wp2);
            fma2(acc0[3], a0, wp3); fma2(acc1[3], a1, wp3);
            fma2(acc0[4], a0, wp4); fma2(acc1[4], a1, wp4);
            fma2(acc0[5], a0, wp5); fma2(acc1[5], a1, wp5);
            fma2(acc0[6], a0, wp6); fma2(acc1[6], a1, wp6);
            fma2(acc0[7], a0, wp7); fma2(acc1[7], a1, wp7);
        }
    }

    // epilogue via smem so global stores are coalesced float4
    __syncthreads();
    #pragma unroll
    for (int p = 0; p < 8; p++) {
        *(float2*)(sa + lane * 132 + c0 + 2 * p)        = upk(acc0[p]);
        *(float2*)(sa + (lane + 32) * 132 + c0 + 2 * p) = upk(acc1[p]);
    }
    __syncthreads();

    float* out = mode ? g_t : g_h;
    #pragma unroll
    for (int i = 0; i < 8; i++) {
        int f = tid + i * 256;      // 2048 float4
        int r = f >> 5, k4 = f & 31;
        int gr = row0 + r;
        if (gr < N_NODES) {
            float4 v = *(const float4*)(sa + r * 132 + k4 * 4);
            if (mode == 0) {
                float4 bb = ((const float4*)bias)[k4];
                v.x += bb.x; v.y += bb.y; v.z += bb.z; v.w += bb.w;
            } else {
                float d = g_dis[gr];
                v.x *= d; v.y *= d; v.z *= d; v.w *= d;
            }
            ((float4*)out)[gr * 32 + k4] = v;
        }
    }
}

// ------- fused CSR gather + residual + relu + LayerNorm (warp per node) -------
// agg[v] = dis[v] * ( sum_{r in N(v)} t'[r] + t'[v] ),  t' = dis*t
// h[v] = LN( h[v] + relu(agg[v] + b) )
__global__ void __launch_bounds__(512) k_gln(const float* __restrict__ b,
                                             const float* __restrict__ gamma,
                                             const float* __restrict__ beta) {
    int v = (blockIdx.x * blockDim.x + threadIdx.x) >> 5;
    if (v >= N_NODES) return;
    int lane = threadIdx.x & 31;
    int col4 = lane * 4;

    float4 acc = *(const float4*)(g_t + v * HID + col4);   // self loop term
    int i = g_off[v], e = g_off[v + 1];
    for (; i + 4 <= e; i += 4) {
        int r0 = __ldg(&g_csr[i]);
        int r1 = __ldg(&g_csr[i + 1]);
        int r2 = __ldg(&g_csr[i + 2]);
        int r3 = __ldg(&g_csr[i + 3]);
        float4 v0 = *(const float4*)(g_t + r0 * HID + col4);
        float4 v1 = *(const float4*)(g_t + r1 * HID + col4);
        float4 v2 = *(const float4*)(g_t + r2 * HID + col4);
        float4 v3 = *(const float4*)(g_t + r3 * HID + col4);
        acc.x += (v0.x + v1.x) + (v2.x + v3.x);
        acc.y += (v0.y + v1.y) + (v2.y + v3.y);
        acc.z += (v0.z + v1.z) + (v2.z + v3.z);
        acc.w += (v0.w + v1.w) + (v2.w + v3.w);
    }
    for (; i < e; i++) {
        int r = __ldg(&g_csr[i]);
        float4 vv = *(const float4*)(g_t + r * HID + col4);
        acc.x += vv.x; acc.y += vv.y; acc.z += vv.z; acc.w += vv.w;
    }

    float dv = g_dis[v];
    float4 hv = *(const float4*)(g_h + v * HID + col4);
    float4 bv = ((const float4*)b)[lane];
    float x0 = hv.x + fmaxf(dv * acc.x + bv.x, 0.f);
    float x1 = hv.y + fmaxf(dv * acc.y + bv.y, 0.f);
    float x2 = hv.z + fmaxf(dv * acc.z + bv.z, 0.f);
    float x3 = hv.w + fmaxf(dv * acc.w + bv.w, 0.f);

    float s = x0 + x1 + x2 + x3;
    #pragma unroll
    for (int off = 16; off > 0; off >>= 1) s += __shfl_xor_sync(0xffffffffu, s, off);
    float mu = s * (1.f / 128.f);
    float d0 = x0 - mu, d1 = x1 - mu, d2 = x2 - mu, d3 = x3 - mu;
    float q = d0 * d0 + d1 * d1 + d2 * d2 + d3 * d3;
    #pragma unroll
    for (int off = 16; off > 0; off >>= 1) q += __shfl_xor_sync(0xffffffffu, q, off);
    float rs = rsqrtf(q * (1.f / 128.f) + LN_EPS);
    float4 gv = ((const float4*)gamma)[lane];
    float4 be = ((const float4*)beta)[lane];
    float4 o;
    o.x = d0 * rs * gv.x + be.x;
    o.y = d1 * rs * gv.y + be.y;
    o.z = d2 * rs * gv.z + be.z;
    o.w = d3 * rs * gv.w + be.w;
    *(float4*)(g_h + v * HID + col4) = o;
}

// ---------------- output head + mean pool (batch sorted -> block-local reduce) -------
__global__ void k_pool(const float* __restrict__ Wout) {
    __shared__ float swv[HID];
    __shared__ float ssum[N_GRAPHS];
    __shared__ int   scnt[N_GRAPHS];
    int tid = threadIdx.x;
    if (tid < HID) swv[tid] = Wout[tid];
    if (tid < N_GRAPHS) { ssum[tid] = 0.f; scnt[tid] = 0; }
    __syncthreads();
    int v = (blockIdx.x * blockDim.x + tid) >> 5;
    int lane = tid & 31;
    if (v < N_NODES) {
        float4 hv = *(const float4*)(g_h + v * HID + lane * 4);
        float4 wv = *(const float4*)(swv + lane * 4);
        float s = hv.x * wv.x + hv.y * wv.y + hv.z * wv.z + hv.w * wv.w;
        #pragma unroll
        for (int off = 16; off > 0; off >>= 1) s += __shfl_xor_sync(0xffffffffu, s, off);
        if (lane == 0) {
            int b = g_batch[v];
            atomicAdd(&ssum[b], s);
            atomicAdd(&scnt[b], 1);
        }
    }
    __syncthreads();
    if (tid < N_GRAPHS && scnt[tid] > 0) {
        atomicAdd(&g_sums[tid], ssum[tid]);
        atomicAdd(&g_cnts[tid], scnt[tid]);
    }
}

__global__ void k_out(float* out) {
    int g = threadIdx.x;
    if (g < N_GRAPHS) out[g] = g_sums[g] / fmaxf((float)g_cnts[g], 1.f);
}

// ---------------- launch ----------------
extern "C" void kernel_launch(void* const* d_in, const int* in_sizes, int n_in,
                              void* d_out, int out_size) {
    const float* x        = (const float*)d_in[0];
    const void*  ei       = d_in[1];
    const void*  batch    = d_in[2];
    const float* W_emb    = (const float*)d_in[3];
    const float* b_emb    = (const float*)d_in[4];
    const float* W_layers = (const float*)d_in[5];
    const float* b_layers = (const float*)d_in[6];
    const float* ln_gamma = (const float*)d_in[7];
    const float* ln_beta  = (const float*)d_in[8];
    const float* W_out    = (const float*)d_in[9];
    float* out = (float*)d_out;

    const int GEMM_SMEM = (128 * 132 + 64 * 132) * sizeof(float);   // 101,376 B
    static int smem_set = 0;
    if (!smem_set) {
        cudaFuncSetAttribute(k_gemm, cudaFuncAttributeMaxDynamicSharedMemorySize, GEMM_SMEM);
        smem_set = 1;
    }

    k_detect<<<1, 32>>>((const unsigned int*)ei);
    k_convert<<<(N_EDGES + 255) / 256, 256>>>(ei, batch);
    k_deg<<<(N_EDGES + 255) / 256, 256>>>();
    k_scan<<<1, 1024>>>();
    k_fill<<<(N_EDGES + 255) / 256, 256>>>();
    k_transpose<<<(5 * HID * HID + 255) / 256, 256>>>(W_emb, W_layers);

    int gemm_blocks = (N_NODES + 63) / 64;
    // device-symbol addresses for A operand
    float* d_h = nullptr;
    cudaGetSymbolAddress((void**)&d_h, g_h);
    const float* Wt = nullptr;
    cudaGetSymbolAddress((void**)&Wt, g_Wt);

    k_gemm<<<gemm_blocks, 256, GEMM_SMEM>>>(x, Wt, b_emb, 0);

    int gln_blocks = (N_NODES * 32 + 511) / 512;
    for (int i = 0; i < 4; i++) {
        k_gemm<<<gemm_blocks, 256, GEMM_SMEM>>>(d_h, Wt + (1 + i) * HID * HID, nullptr, 1);
        k_gln<<<gln_blocks, 512>>>(b_layers + i * HID, ln_gamma + i * HID, ln_beta + i * HID);
    }

    k_pool<<<(N_NODES * 32 + 511) / 512, 512>>>(W_out);
    k_out<<<1, 32>>>(out);
}

// round 3
// speedup vs baseline: 1.7807x; 1.3052x over previous
#include <cuda_runtime.h>

#define N_NODES 50000
#define N_EDGES 800000
#define HID     128
#define N_GRAPHS 32
#define LN_EPS  1e-5f
#define NBLK    196          // ceil(50000/256) scan blocks

typedef unsigned long long ull;

// ---------------- scratch (device globals; no allocations allowed) ----------------
__device__ float g_h[N_NODES * HID];
__device__ float g_t[N_NODES * HID];       // t' = dis[v] * (h W^T)
__device__ float g_Wt[5 * HID * HID];      // transposed weights Wt[k][o]
__device__ float g_dis[N_NODES];
__device__ int   g_edeg[N_NODES];          // edge-only in-degree (self-loop excluded)
__device__ int   g_off[N_NODES + 1];
__device__ int   g_cursor[N_NODES];
__device__ int   g_csr[N_EDGES];           // source rows grouped by target col
__device__ int   g_row[N_EDGES];
__device__ int   g_col[N_EDGES];
__device__ int   g_batch[N_NODES];
__device__ int   g_bsum[NBLK];
__device__ int   g_bpre[NBLK];
__device__ float g_sums[N_GRAPHS];
__device__ int   g_cnts[N_GRAPHS];
__device__ int   g_flag64;

// ---------------- packed f32x2 FMA helpers (Blackwell FFMA2) ----------------
__device__ __forceinline__ ull pk(float lo, float hi) {
    ull r; asm("mov.b64 %0, {%1,%2};" : "=l"(r) : "f"(lo), "f"(hi)); return r;
}
__device__ __forceinline__ void fma2(ull& d, ull a, ull b) {
    asm("fma.rn.f32x2 %0, %1, %2, %0;" : "+l"(d) : "l"(a), "l"(b));
}
__device__ __forceinline__ float2 upk(ull v) {
    float2 f; asm("mov.b64 {%0,%1}, %2;" : "=f"(f.x), "=f"(f.y) : "l"(v)); return f;
}
__device__ __forceinline__ float comp(const float4& v, int i) {
    return i == 0 ? v.x : (i == 1 ? v.y : (i == 2 ? v.z : v.w));
}

// ---------------- dtype detection: int64 indices have zero high words (parallel) ----
__global__ void k_detect(const unsigned int* ei) {
    int lane = threadIdx.x;
    unsigned ok = 1;
    #pragma unroll
    for (int j = 0; j < 4; j++) {
        int idx = 1 + 2 * (lane * 4 + j);      // odd words of first 256 words
        ok &= (ei[idx] == 0u);
    }
    unsigned all = __ballot_sync(0xffffffffu, ok != 0);
    if (lane == 0) g_flag64 = (all == 0xffffffffu);
}

// convert indices; zero edeg; load batch; zero pool accumulators
__global__ void k_convert(const void* ei, const void* batch) {
    int i = blockIdx.x * blockDim.x + threadIdx.x;
    int f64 = g_flag64;
    if (i < N_EDGES) {
        if (f64) {
            const long long* p = (const long long*)ei;
            g_row[i] = (int)p[i];
            g_col[i] = (int)p[N_EDGES + i];
        } else {
            const int* p = (const int*)ei;
            g_row[i] = p[i];
            g_col[i] = p[N_EDGES + i];
        }
    }
    if (i < N_NODES) {
        int b = f64 ? (int)((const long long*)batch)[i] : ((const int*)batch)[i];
        g_batch[i] = b;
        g_edeg[i] = 0;
    }
    if (i < N_GRAPHS) { g_sums[i] = 0.f; g_cnts[i] = 0; }
}

__global__ void k_deg() {
    int e = blockIdx.x * blockDim.x + threadIdx.x;
    if (e < N_EDGES) atomicAdd(&g_edeg[g_col[e]], 1);
}

// ---------------- parallel scan: blocksum -> scan partials -> offsets ----------------
__global__ void __launch_bounds__(256) k_blocksum() {
    __shared__ int ws[8];
    int v = blockIdx.x * 256 + threadIdx.x;
    int d = (v < N_NODES) ? g_edeg[v] : 0;
    int x = d;
    #pragma unroll
    for (int off = 1; off < 32; off <<= 1) {
        int y = __shfl_up_sync(0xffffffffu, x, off);
        if ((threadIdx.x & 31) >= off) x += y;
    }
    if ((threadIdx.x & 31) == 31) ws[threadIdx.x >> 5] = x;
    __syncthreads();
    if (threadIdx.x == 0) {
        int s = 0;
        #pragma unroll
        for (int i = 0; i < 8; i++) s += ws[i];
        g_bsum[blockIdx.x] = s;
    }
}

__global__ void __launch_bounds__(256) k_scanb() {
    __shared__ int ws[8];
    int tid = threadIdx.x;
    int d = (tid < NBLK) ? g_bsum[tid] : 0;
    int lane = tid & 31, wid = tid >> 5;
    int x = d;
    #pragma unroll
    for (int off = 1; off < 32; off <<= 1) {
        int y = __shfl_up_sync(0xffffffffu, x, off);
        if (lane >= off) x += y;
    }
    if (lane == 31) ws[wid] = x;
    __syncthreads();
    if (tid == 0) {
        int run = 0;
        #pragma unroll
        for (int i = 0; i < 8; i++) { int t = ws[i]; ws[i] = run; run += t; }
        g_off[N_NODES] = run;          // total edge count
    }
    __syncthreads();
    if (tid < NBLK) g_bpre[tid] = x - d + ws[wid];   // exclusive prefix
}

__global__ void __launch_bounds__(256) k_offsets() {
    __shared__ int ws[8];
    int tid = threadIdx.x;
    int v = blockIdx.x * 256 + tid;
    int d = (v < N_NODES) ? g_edeg[v] : 0;
    int lane = tid & 31, wid = tid >> 5;
    int x = d;
    #pragma unroll
    for (int off = 1; off < 32; off <<= 1) {
        int y = __shfl_up_sync(0xffffffffu, x, off);
        if (lane >= off) x += y;
    }
    if (lane == 31) ws[wid] = x;
    __syncthreads();
    if (tid == 0) {
        int run = 0;
        #pragma unroll
        for (int i = 0; i < 8; i++) { int t = ws[i]; ws[i] = run; run += t; }
    }
    __syncthreads();
    if (v < N_NODES) {
        int excl = x - d + ws[wid] + g_bpre[blockIdx.x];
        g_off[v] = excl;
        g_cursor[v] = excl;
        g_dis[v] = rsqrtf((float)(d + 1));
    }
}

__global__ void k_fill() {
    int e = blockIdx.x * blockDim.x + threadIdx.x;
    if (e < N_EDGES) {
        int c = g_col[e];
        int pos = atomicAdd(&g_cursor[c], 1);
        g_csr[pos] = g_row[e];
    }
}

// transpose all 5 weight matrices: g_Wt[w][k][o] = W[w][o][k]
__global__ void k_transpose(const float* __restrict__ W_emb, const float* __restrict__ W_layers) {
    int i = blockIdx.x * blockDim.x + threadIdx.x;
    if (i >= 5 * HID * HID) return;
    int w = i >> 14, r = i & 16383;
    float v = (w == 0) ? W_emb[r] : W_layers[(w - 1) * 16384 + r];
    int o = r >> 7, k = r & 127;
    g_Wt[w * 16384 + k * HID + o] = v;
}

// ---------------- GEMM: out[n][o] = sum_k A[n][k] * Wt[k][o]  ----------------
__global__ void __launch_bounds__(256) k_gemm(const float* __restrict__ A,
                                              const float* __restrict__ Wt,
                                              const float* __restrict__ bias,
                                              int mode) {
    extern __shared__ float sm[];
    float* sw = sm;                 // 128 x 132  (sw[k*132+o] = Wt[k][o])
    float* sa = sm + 128 * 132;     // 64 x 132

    int tid = threadIdx.x;
    int row0 = blockIdx.x * 64;

    #pragma unroll
    for (int i = 0; i < 16; i++) {
        int f = tid + i * 256;
        int k = f >> 5, o4 = f & 31;
        float4 v = ((const float4*)Wt)[f];
        *(float4*)(sw + k * 132 + o4 * 4) = v;
    }
    #pragma unroll
    for (int i = 0; i < 8; i++) {
        int f = tid + i * 256;
        int r = f >> 5, k4 = f & 31;
        int gr = row0 + r;
        float4 v = (gr < N_NODES) ? ((const float4*)A)[gr * 32 + k4]
                                  : make_float4(0.f, 0.f, 0.f, 0.f);
        *(float4*)(sa + r * 132 + k4 * 4) = v;
    }
    __syncthreads();

    int lane = tid & 31, warp = tid >> 5;
    int c0 = warp * 16;

    ull acc0[8], acc1[8];
    #pragma unroll
    for (int p = 0; p < 8; p++) { acc0[p] = 0ULL; acc1[p] = 0ULL; }

    #pragma unroll 2
    for (int k4 = 0; k4 < 32; k4++) {
        float4 aA = *(const float4*)(sa + lane * 132 + k4 * 4);
        float4 aB = *(const float4*)(sa + (lane + 32) * 132 + k4 * 4);
        #pragma unroll
        for (int kk = 0; kk < 4; kk++) {
            const float* wr = sw + (k4 * 4 + kk) * 132 + c0;
            float4 w0 = *(const float4*)(wr);
            float4 w1 = *(const float4*)(wr + 4);
            float4 w2 = *(const float4*)(wr + 8);
            float4 w3 = *(const float4*)(wr + 12);
            float avA = comp(aA, kk), avB = comp(aB, kk);
            ull a0 = pk(avA, avA), a1 = pk(avB, avB);
            ull wp0 = pk(w0.x, w0.y), wp1 = pk(w0.z, w0.w);
            ull wp2 = pk(w1.x, w1.y), wp3 = pk(w1.z, w1.w);
            ull wp4 = pk(w2.x, w2.y), wp5 = pk(w2.z, w2.w);
            ull wp6 = pk(w3.x, w3.y), wp7 = pk(w3.z, w3.w);
            fma2(acc0[0], a0, wp0); fma2(acc1[0], a1, wp0);
            fma2(acc0[1], a0, wp1); fma2(acc1[1], a1, wp1);
            fma2(acc0[2], a0, wp2); fma2(acc1[2], a1, wp2);
            fma2(acc0[3], a0, wp3); fma2(acc1[3], a1, wp3);
            fma2(acc0[4], a0, wp4); fma2(acc1[4], a1, wp4);
            fma2(acc0[5], a0, wp5); fma2(acc1[5], a1, wp5);
            fma2(acc0[6], a0, wp6); fma2(acc1[6], a1, wp6);
            fma2(acc0[7], a0, wp7); fma2(acc1[7], a1, wp7);
        }
    }

    __syncthreads();
    #pragma unroll
    for (int p = 0; p < 8; p++) {
        *(float2*)(sa + lane * 132 + c0 + 2 * p)        = upk(acc0[p]);
        *(float2*)(sa + (lane + 32) * 132 + c0 + 2 * p) = upk(acc1[p]);
    }
    __syncthreads();

    float* out = mode ? g_t : g_h;
    #pragma unroll
    for (int i = 0; i < 8; i++) {
        int f = tid + i * 256;
        int r = f >> 5, k4 = f & 31;
        int gr = row0 + r;
        if (gr < N_NODES) {
            float4 v = *(const float4*)(sa + r * 132 + k4 * 4);
            if (mode == 0) {
                float4 bb = ((const float4*)bias)[k4];
                v.x += bb.x; v.y += bb.y; v.z += bb.z; v.w += bb.w;
            } else {
                float d = g_dis[gr];
                v.x *= d; v.y *= d; v.z *= d; v.w *= d;
            }
            ((float4*)out)[gr * 32 + k4] = v;
        }
    }
}

// ------- fused CSR gather + residual + relu + LayerNorm (+ optional pool) -------
// warp per node; 3125 blocks x 16 warps covers 50000 exactly
__global__ void __launch_bounds__(512) k_gln(const float* __restrict__ b,
                                             const float* __restrict__ gamma,
                                             const float* __restrict__ beta,
                                             const float* __restrict__ Wout) {
    __shared__ float ssum[N_GRAPHS];
    __shared__ int   scnt[N_GRAPHS];
    const bool pool = (Wout != nullptr);
    int tid = threadIdx.x;
    if (pool) {
        if (tid < N_GRAPHS) { ssum[tid] = 0.f; scnt[tid] = 0; }
        __syncthreads();
    }

    int v = (blockIdx.x * blockDim.x + tid) >> 5;
    int lane = tid & 31;
    int col4 = lane * 4;
    bool active = (v < N_NODES);
    float4 o = make_float4(0.f, 0.f, 0.f, 0.f);

    if (active) {
        float4 acc = *(const float4*)(g_t + v * HID + col4);   // self loop
        int i = g_off[v], e = g_off[v + 1];
        for (; i + 4 <= e; i += 4) {
            int r0 = __ldg(&g_csr[i]);
            int r1 = __ldg(&g_csr[i + 1]);
            int r2 = __ldg(&g_csr[i + 2]);
            int r3 = __ldg(&g_csr[i + 3]);
            float4 v0 = *(const float4*)(g_t + r0 * HID + col4);
            float4 v1 = *(const float4*)(g_t + r1 * HID + col4);
            float4 v2 = *(const float4*)(g_t + r2 * HID + col4);
            float4 v3 = *(const float4*)(g_t + r3 * HID + col4);
            acc.x += (v0.x + v1.x) + (v2.x + v3.x);
            acc.y += (v0.y + v1.y) + (v2.y + v3.y);
            acc.z += (v0.z + v1.z) + (v2.z + v3.z);
            acc.w += (v0.w + v1.w) + (v2.w + v3.w);
        }
        for (; i < e; i++) {
            int r = __ldg(&g_csr[i]);
            float4 vv = *(const float4*)(g_t + r * HID + col4);
            acc.x += vv.x; acc.y += vv.y; acc.z += vv.z; acc.w += vv.w;
        }

        float dv = g_dis[v];
        float4 hv = *(const float4*)(g_h + v * HID + col4);
        float4 bv = ((const float4*)b)[lane];
        float x0 = hv.x + fmaxf(dv * acc.x + bv.x, 0.f);
        float x1 = hv.y + fmaxf(dv * acc.y + bv.y, 0.f);
        float x2 = hv.z + fmaxf(dv * acc.z + bv.z, 0.f);
        float x3 = hv.w + fmaxf(dv * acc.w + bv.w, 0.f);

        float s = x0 + x1 + x2 + x3;
        #pragma unroll
        for (int off = 16; off > 0; off >>= 1) s += __shfl_xor_sync(0xffffffffu, s, off);
        float mu = s * (1.f / 128.f);
        float d0 = x0 - mu, d1 = x1 - mu, d2 = x2 - mu, d3 = x3 - mu;
        float q = d0 * d0 + d1 * d1 + d2 * d2 + d3 * d3;
        #pragma unroll
        for (int off = 16; off > 0; off >>= 1) q += __shfl_xor_sync(0xffffffffu, q, off);
        float rs = rsqrtf(q * (1.f / 128.f) + LN_EPS);
        float4 gv = ((const float4*)gamma)[lane];
        float4 be = ((const float4*)beta)[lane];
        o.x = d0 * rs * gv.x + be.x;
        o.y = d1 * rs * gv.y + be.y;
        o.z = d2 * rs * gv.z + be.z;
        o.w = d3 * rs * gv.w + be.w;
        *(float4*)(g_h + v * HID + col4) = o;
    }

    if (pool) {
        float s = 0.f;
        if (active) {
            float4 wv = ((const float4*)Wout)[lane];
            s = o.x * wv.x + o.y * wv.y + o.z * wv.z + o.w * wv.w;
        }
        #pragma unroll
        for (int off = 16; off > 0; off >>= 1) s += __shfl_xor_sync(0xffffffffu, s, off);
        if (active && lane == 0) {
            int bg = g_batch[v];
            atomicAdd(&ssum[bg], s);
            atomicAdd(&scnt[bg], 1);
        }
        __syncthreads();
        if (tid < N_GRAPHS && scnt[tid] > 0) {
            atomicAdd(&g_sums[tid], ssum[tid]);
            atomicAdd(&g_cnts[tid], scnt[tid]);
        }
    }
}

__global__ void k_out(float* out) {
    int g = threadIdx.x;
    if (g < N_GRAPHS) out[g] = g_sums[g] / fmaxf((float)g_cnts[g], 1.f);
}

// ---------------- launch ----------------
extern "C" void kernel_launch(void* const* d_in, const int* in_sizes, int n_in,
                              void* d_out, int out_size) {
    const float* x        = (const float*)d_in[0];
    const void*  ei       = d_in[1];
    const void*  batch    = d_in[2];
    const float* W_emb    = (const float*)d_in[3];
    const float* b_emb    = (const float*)d_in[4];
    const float* W_layers = (const float*)d_in[5];
    const float* b_layers = (const float*)d_in[6];
    const float* ln_gamma = (const float*)d_in[7];
    const float* ln_beta  = (const float*)d_in[8];
    const float* W_out    = (const float*)d_in[9];
    float* out = (float*)d_out;

    const int GEMM_SMEM = (128 * 132 + 64 * 132) * sizeof(float);   // 101,376 B
    static int smem_set = 0;
    if (!smem_set) {
        cudaFuncSetAttribute(k_gemm, cudaFuncAttributeMaxDynamicSharedMemorySize, GEMM_SMEM);
        smem_set = 1;
    }

    k_detect<<<1, 32>>>((const unsigned int*)ei);
    k_convert<<<(N_EDGES + 255) / 256, 256>>>(ei, batch);
    k_deg<<<(N_EDGES + 255) / 256, 256>>>();
    k_blocksum<<<NBLK, 256>>>();
    k_scanb<<<1, 256>>>();
    k_offsets<<<NBLK, 256>>>();
    k_fill<<<(N_EDGES + 255) / 256, 256>>>();
    k_transpose<<<(5 * HID * HID + 255) / 256, 256>>>(W_emb, W_layers);

    int gemm_blocks = (N_NODES + 63) / 64;
    float* d_h = nullptr;
    cudaGetSymbolAddress((void**)&d_h, g_h);
    const float* Wt = nullptr;
    cudaGetSymbolAddress((void**)&Wt, g_Wt);

    k_gemm<<<gemm_blocks, 256, GEMM_SMEM>>>(x, Wt, b_emb, 0);

    int gln_blocks = (N_NODES + 15) / 16;    // 3125
    for (int i = 0; i < 4; i++) {
        k_gemm<<<gemm_blocks, 256, GEMM_SMEM>>>(d_h, Wt + (1 + i) * HID * HID, nullptr, 1);
        k_gln<<<gln_blocks, 512>>>(b_layers + i * HID, ln_gamma + i * HID, ln_beta + i * HID,
                                   (i == 3) ? W_out : nullptr);
    }

    k_out<<<1, 32>>>(out);
}

// round 5
// speedup vs baseline: 1.9167x; 1.0764x over previous
#include <cuda_runtime.h>
#include <cstdint>

#define N_NODES 50000
#define N_EDGES 800000
#define HID     128
#define N_GRAPHS 32
#define LN_EPS  1e-5f
#define NBLK    196          // ceil(50000/256) scan blocks

typedef unsigned int u32;
typedef unsigned long long ull;

// ---------------- scratch (device globals; no allocations allowed) ----------------
__device__ float g_h[N_NODES * HID];
__device__ __align__(16) u32 g_tb[N_NODES * HID / 2];   // t' as bf16x2 (halved gather traffic)
__device__ float g_Wt[5 * HID * HID];      // transposed weights Wt[k][o]
__device__ float g_dis[N_NODES];
__device__ int   g_edeg[N_NODES];
__device__ int   g_off[N_NODES + 1];
__device__ int   g_cursor[N_NODES];
__device__ int   g_csr[N_EDGES];
__device__ int   g_row[N_EDGES];
__device__ int   g_col[N_EDGES];
__device__ int   g_batch[N_NODES];
__device__ int   g_bsum[NBLK];
__device__ int   g_bpre[NBLK];
__device__ float g_sums[N_GRAPHS];
__device__ int   g_cnts[N_GRAPHS];
__device__ int   g_flag64;

// ---------------- packed f32x2 FMA helpers (Blackwell FFMA2) ----------------
__device__ __forceinline__ ull pk(float lo, float hi) {
    ull r; asm("mov.b64 %0, {%1,%2};" : "=l"(r) : "f"(lo), "f"(hi)); return r;
}
__device__ __forceinline__ void fma2(ull& d, ull a, ull b) {
    asm("fma.rn.f32x2 %0, %1, %2, %0;" : "+l"(d) : "l"(a), "l"(b));
}
__device__ __forceinline__ float2 upk(ull v) {
    float2 f; asm("mov.b64 {%0,%1}, %2;" : "=f"(f.x), "=f"(f.y) : "l"(v)); return f;
}
__device__ __forceinline__ float comp(const float4& v, int i) {
    return i == 0 ? v.x : (i == 1 ? v.y : (i == 2 ? v.z : v.w));
}
// cvt.rn.bf16x2.f32 d, a, b : d.hi = bf16(a), d.lo = bf16(b)
__device__ __forceinline__ u32 cvt2(float hi_elem, float lo_elem) {
    u32 r; asm("cvt.rn.bf16x2.f32 %0, %1, %2;" : "=r"(r) : "f"(hi_elem), "f"(lo_elem)); return r;
}
__device__ __forceinline__ float bf_lo(u32 v) { return __uint_as_float(v << 16); }
__device__ __forceinline__ float bf_hi(u32 v) { return __uint_as_float(v & 0xffff0000u); }

// ---------------- dtype detection: int64 indices have zero high words ----------------
__global__ void k_detect(const unsigned int* ei) {
    int lane = threadIdx.x;
    unsigned ok = 1;
    #pragma unroll
    for (int j = 0; j < 4; j++) ok &= (ei[1 + 2 * (lane * 4 + j)] == 0u);
    unsigned all = __ballot_sync(0xffffffffu, ok != 0);
    if (lane == 0) g_flag64 = (all == 0xffffffffu);
}

// convert indices + accumulate degree (fused); load batch; zero pool accumulators
__global__ void k_convert(const void* ei, const void* batch) {
    int i = blockIdx.x * blockDim.x + threadIdx.x;
    int f64 = g_flag64;
    if (i < N_NODES) {
        int b = f64 ? (int)((const long long*)batch)[i] : ((const int*)batch)[i];
        g_batch[i] = b;
        g_edeg[i] = 0;
    }
    if (i < N_GRAPHS) { g_sums[i] = 0.f; g_cnts[i] = 0; }
    // grid-wide: ensure edeg zeroing of *this block's* range doesn't race with
    // another block's atomicAdd -> use a separate pass trick: zero first in a
    // different kernel would cost a launch; instead zero via the fact that all
    // writes here precede the atomics of the SAME kernel only within a block.
    // To stay safe we split: blocks [0, NBLK) zero edeg; all blocks then do
    // edge atomics AFTER a device-wide dependency cannot be expressed -> so
    // instead we keep the zeroing in this kernel but do the deg atomics in
    // k_fill's precursor (k_deg2) below. (deg atomics moved to k_deg2)
    if (i < N_EDGES) {
        if (f64) {
            const long long* p = (const long long*)ei;
            g_row[i] = (int)p[i];
            g_col[i] = (int)p[N_EDGES + i];
        } else {
            const int* p = (const int*)ei;
            g_row[i] = p[i];
            g_col[i] = p[N_EDGES + i];
        }
    }
}

__global__ void k_deg2() {
    int e = blockIdx.x * blockDim.x + threadIdx.x;
    if (e < N_EDGES) atomicAdd(&g_edeg[g_col[e]], 1);
}

// ---------------- parallel scan ----------------
__global__ void __launch_bounds__(256) k_blocksum() {
    __shared__ int ws[8];
    int v = blockIdx.x * 256 + threadIdx.x;
    int d = (v < N_NODES) ? g_edeg[v] : 0;
    int x = d;
    #pragma unroll
    for (int off = 1; off < 32; off <<= 1) {
        int y = __shfl_up_sync(0xffffffffu, x, off);
        if ((threadIdx.x & 31) >= off) x += y;
    }
    if ((threadIdx.x & 31) == 31) ws[threadIdx.x >> 5] = x;
    __syncthreads();
    if (threadIdx.x == 0) {
        int s = 0;
        #pragma unroll
        for (int i = 0; i < 8; i++) s += ws[i];
        g_bsum[blockIdx.x] = s;
    }
}

__global__ void __launch_bounds__(256) k_scanb() {
    __shared__ int ws[8];
    int tid = threadIdx.x;
    int d = (tid < NBLK) ? g_bsum[tid] : 0;
    int lane = tid & 31, wid = tid >> 5;
    int x = d;
    #pragma unroll
    for (int off = 1; off < 32; off <<= 1) {
        int y = __shfl_up_sync(0xffffffffu, x, off);
        if (lane >= off) x += y;
    }
    if (lane == 31) ws[wid] = x;
    __syncthreads();
    if (tid == 0) {
        int run = 0;
        #pragma unroll
        for (int i = 0; i < 8; i++) { int t = ws[i]; ws[i] = run; run += t; }
        g_off[N_NODES] = run;
    }
    __syncthreads();
    if (tid < NBLK) g_bpre[tid] = x - d + ws[wid];
}

__global__ void __launch_bounds__(256) k_offsets() {
    __shared__ int ws[8];
    int tid = threadIdx.x;
    int v = blockIdx.x * 256 + tid;
    int d = (v < N_NODES) ? g_edeg[v] : 0;
    int lane = tid & 31, wid = tid >> 5;
    int x = d;
    #pragma unroll
    for (int off = 1; off < 32; off <<= 1) {
        int y = __shfl_up_sync(0xffffffffu, x, off);
        if (lane >= off) x += y;
    }
    if (lane == 31) ws[wid] = x;
    __syncthreads();
    if (tid == 0) {
        int run = 0;
        #pragma unroll
        for (int i = 0; i < 8; i++) { int t = ws[i]; ws[i] = run; run += t; }
    }
    __syncthreads();
    if (v < N_NODES) {
        int excl = x - d + ws[wid] + g_bpre[blockIdx.x];
        g_off[v] = excl;
        g_cursor[v] = excl;
        g_dis[v] = rsqrtf((float)(d + 1));
    }
}

__global__ void k_fill() {
    int e = blockIdx.x * blockDim.x + threadIdx.x;
    if (e < N_EDGES) {
        int c = g_col[e];
        int pos = atomicAdd(&g_cursor[c], 1);
        g_csr[pos] = g_row[e];
    }
}

// transpose all 5 weight matrices: g_Wt[w][k][o] = W[w][o][k]
__global__ void k_transpose(const float* __restrict__ W_emb, const float* __restrict__ W_layers) {
    int i = blockIdx.x * blockDim.x + threadIdx.x;
    if (i >= 5 * HID * HID) return;
    int w = i >> 14, r = i & 16383;
    float v = (w == 0) ? W_emb[r] : W_layers[(w - 1) * 16384 + r];
    int o = r >> 7, k = r & 127;
    g_Wt[w * 16384 + k * HID + o] = v;
}

// ---------------- GEMM: out[n][o] = sum_k A[n][k] * Wt[k][o]  ----------------
// mode 0: g_h = A Wt + bias (fp32). mode 1: g_tb = bf16x2( dis[row] * (A Wt) ).
__global__ void __launch_bounds__(256) k_gemm(const float* __restrict__ A,
                                              const float* __restrict__ Wt,
                                              const float* __restrict__ bias,
                                              int mode) {
    extern __shared__ float sm[];
    float* sw = sm;                 // 128 x 132  (sw[k*132+o] = Wt[k][o])
    float* sa = sm + 128 * 132;     // 64 x 132

    int tid = threadIdx.x;
    int row0 = blockIdx.x * 64;

    #pragma unroll
    for (int i = 0; i < 16; i++) {
        int f = tid + i * 256;
        int k = f >> 5, o4 = f & 31;
        float4 v = ((const float4*)Wt)[f];
        *(float4*)(sw + k * 132 + o4 * 4) = v;
    }
    #pragma unroll
    for (int i = 0; i < 8; i++) {
        int f = tid + i * 256;
        int r = f >> 5, k4 = f & 31;
        int gr = row0 + r;
        float4 v = (gr < N_NODES) ? ((const float4*)A)[gr * 32 + k4]
                                  : make_float4(0.f, 0.f, 0.f, 0.f);
        *(float4*)(sa + r * 132 + k4 * 4) = v;
    }
    __syncthreads();

    int lane = tid & 31, warp = tid >> 5;
    int c0 = warp * 16;

    ull acc0[8], acc1[8];
    #pragma unroll
    for (int p = 0; p < 8; p++) { acc0[p] = 0ULL; acc1[p] = 0ULL; }

    #pragma unroll 2
    for (int k4 = 0; k4 < 32; k4++) {
        float4 aA = *(const float4*)(sa + lane * 132 + k4 * 4);
        float4 aB = *(const float4*)(sa + (lane + 32) * 132 + k4 * 4);
        #pragma unroll
        for (int kk = 0; kk < 4; kk++) {
            const float* wr = sw + (k4 * 4 + kk) * 132 + c0;
            float4 w0 = *(const float4*)(wr);
            float4 w1 = *(const float4*)(wr + 4);
            float4 w2 = *(const float4*)(wr + 8);
            float4 w3 = *(const float4*)(wr + 12);
            float avA = comp(aA, kk), avB = comp(aB, kk);
            ull a0 = pk(avA, avA), a1 = pk(avB, avB);
            ull wp0 = pk(w0.x, w0.y), wp1 = pk(w0.z, w0.w);
            ull wp2 = pk(w1.x, w1.y), wp3 = pk(w1.z, w1.w);
            ull wp4 = pk(w2.x, w2.y), wp5 = pk(w2.z, w2.w);
            ull wp6 = pk(w3.x, w3.y), wp7 = pk(w3.z, w3.w);
            fma2(acc0[0], a0, wp0); fma2(acc1[0], a1, wp0);
            fma2(acc0[1], a0, wp1); fma2(acc1[1], a1, wp1);
            fma2(acc0[2], a0, wp2); fma2(acc1[2], a1, wp2);
            fma2(acc0[3], a0, wp3); fma2(acc1[3], a1, wp3);
            fma2(acc0[4], a0, wp4); fma2(acc1[4], a1, wp4);
            fma2(acc0[5], a0, wp5); fma2(acc1[5], a1, wp5);
            fma2(acc0[6], a0, wp6); fma2(acc1[6], a1, wp6);
            fma2(acc0[7], a0, wp7); fma2(acc1[7], a1, wp7);
        }
    }

    __syncthreads();
    #pragma unroll
    for (int p = 0; p < 8; p++) {
        *(float2*)(sa + lane * 132 + c0 + 2 * p)        = upk(acc0[p]);
        *(float2*)(sa + (lane + 32) * 132 + c0 + 2 * p) = upk(acc1[p]);
    }
    __syncthreads();

    #pragma unroll
    for (int i = 0; i < 8; i++) {
        int f = tid + i * 256;
        int r = f >> 5, k4 = f & 31;
        int gr = row0 + r;
        if (gr < N_NODES) {
            float4 v = *(const float4*)(sa + r * 132 + k4 * 4);
            if (mode == 0) {
                float4 bb = ((const float4*)bias)[k4];
                v.x += bb.x; v.y += bb.y; v.z += bb.z; v.w += bb.w;
                ((float4*)g_h)[gr * 32 + k4] = v;
            } else {
                float d = g_dis[gr];
                uint2 o;
                o.x = cvt2(v.y * d, v.x * d);
                o.y = cvt2(v.w * d, v.z * d);
                ((uint2*)g_tb)[gr * 32 + k4] = o;
            }
        }
    }
}

// ------- fused CSR gather (bf16 msgs) + residual + relu + LayerNorm (+pool) -------
// warp per node; 3125 blocks x 16 warps covers 50000 exactly
__global__ void __launch_bounds__(512) k_gln(const float* __restrict__ b,
                                             const float* __restrict__ gamma,
                                             const float* __restrict__ beta,
                                             const float* __restrict__ Wout) {
    __shared__ float ssum[N_GRAPHS];
    __shared__ int   scnt[N_GRAPHS];
    const bool pool = (Wout != nullptr);
    int tid = threadIdx.x;
    if (pool) {
        if (tid < N_GRAPHS) { ssum[tid] = 0.f; scnt[tid] = 0; }
        __syncthreads();
    }

    int v = (blockIdx.x * blockDim.x + tid) >> 5;
    int lane = tid & 31;
    bool active = (v < N_NODES);
    float4 o = make_float4(0.f, 0.f, 0.f, 0.f);

    if (active) {
        const uint2* T = (const uint2*)g_tb;
        uint2 sv = T[v * 32 + lane];                 // self loop (bf16x2 pair)
        float a0 = bf_lo(sv.x), a1 = bf_hi(sv.x), a2 = bf_lo(sv.y), a3 = bf_hi(sv.y);

        int i = g_off[v], e = g_off[v + 1];
        for (; i + 4 <= e; i += 4) {
            int r0 = __ldg(&g_csr[i]);
            int r1 = __ldg(&g_csr[i + 1]);
            int r2 = __ldg(&g_csr[i + 2]);
            int r3 = __ldg(&g_csr[i + 3]);
            uint2 m0 = T[r0 * 32 + lane];
            uint2 m1 = T[r1 * 32 + lane];
            uint2 m2 = T[r2 * 32 + lane];
            uint2 m3 = T[r3 * 32 + lane];
            a0 += (bf_lo(m0.x) + bf_lo(m1.x)) + (bf_lo(m2.x) + bf_lo(m3.x));
            a1 += (bf_hi(m0.x) + bf_hi(m1.x)) + (bf_hi(m2.x) + bf_hi(m3.x));
            a2 += (bf_lo(m0.y) + bf_lo(m1.y)) + (bf_lo(m2.y) + bf_lo(m3.y));
            a3 += (bf_hi(m0.y) + bf_hi(m1.y)) + (bf_hi(m2.y) + bf_hi(m3.y));
        }
        for (; i < e; i++) {
            int r = __ldg(&g_csr[i]);
            uint2 m = T[r * 32 + lane];
            a0 += bf_lo(m.x); a1 += bf_hi(m.x); a2 += bf_lo(m.y); a3 += bf_hi(m.y);
        }

        float dv = g_dis[v];
        float4 hv = *(const float4*)(g_h + v * HID + lane * 4);
        float4 bv = ((const float4*)b)[lane];
        float x0 = hv.x + fmaxf(dv * a0 + bv.x, 0.f);
        float x1 = hv.y + fmaxf(dv * a1 + bv.y, 0.f);
        float x2 = hv.z + fmaxf(dv * a2 + bv.z, 0.f);
        float x3 = hv.w + fmaxf(dv * a3 + bv.w, 0.f);

        float s = x0 + x1 + x2 + x3;
        #pragma unroll
        for (int off = 16; off > 0; off >>= 1) s += __shfl_xor_sync(0xffffffffu, s, off);
        float mu = s * (1.f / 128.f);
        float d0 = x0 - mu, d1 = x1 - mu, d2 = x2 - mu, d3 = x3 - mu;
        float q = d0 * d0 + d1 * d1 + d2 * d2 + d3 * d3;
        #pragma unroll
        for (int off = 16; off > 0; off >>= 1) q += __shfl_xor_sync(0xffffffffu, q, off);
        float rs = rsqrtf(q * (1.f / 128.f) + LN_EPS);
        float4 gv = ((const float4*)gamma)[lane];
        float4 be = ((const float4*)beta)[lane];
        o.x = d0 * rs * gv.x + be.x;
        o.y = d1 * rs * gv.y + be.y;
        o.z = d2 * rs * gv.z + be.z;
        o.w = d3 * rs * gv.w + be.w;
        *(float4*)(g_h + v * HID + lane * 4) = o;
    }

    if (pool) {
        float s = 0.f;
        if (active) {
            float4 wv = ((const float4*)Wout)[lane];
            s = o.x * wv.x + o.y * wv.y + o.z * wv.z + o.w * wv.w;
        }
        #pragma unroll
        for (int off = 16; off > 0; off >>= 1) s += __shfl_xor_sync(0xffffffffu, s, off);
        if (active && lane == 0) {
            int bg = g_batch[v];
            atomicAdd(&ssum[bg], s);
            atomicAdd(&scnt[bg], 1);
        }
        __syncthreads();
        if (tid < N_GRAPHS && scnt[tid] > 0) {
            atomicAdd(&g_sums[tid], ssum[tid]);
            atomicAdd(&g_cnts[tid], scnt[tid]);
        }
    }
}

__global__ void k_out(float* out) {
    int g = threadIdx.x;
    if (g < N_GRAPHS) out[g] = g_sums[g] / fmaxf((float)g_cnts[g], 1.f);
}

// ---------------- launch ----------------
extern "C" void kernel_launch(void* const* d_in, const int* in_sizes, int n_in,
                              void* d_out, int out_size) {
    const float* x        = (const float*)d_in[0];
    const void*  ei       = d_in[1];
    const void*  batch    = d_in[2];
    const float* W_emb    = (const float*)d_in[3];
    const float* b_emb    = (const float*)d_in[4];
    const float* W_layers = (const float*)d_in[5];
    const float* b_layers = (const float*)d_in[6];
    const float* ln_gamma = (const float*)d_in[7];
    const float* ln_beta  = (const float*)d_in[8];
    const float* W_out    = (const float*)d_in[9];
    float* out = (float*)d_out;

    const int GEMM_SMEM = (128 * 132 + 64 * 132) * sizeof(float);   // 101,376 B
    static int smem_set = 0;
    if (!smem_set) {
        cudaFuncSetAttribute(k_gemm, cudaFuncAttributeMaxDynamicSharedMemorySize, GEMM_SMEM);
        smem_set = 1;
    }

    k_detect<<<1, 32>>>((const unsigned int*)ei);
    k_convert<<<(N_EDGES + 255) / 256, 256>>>(ei, batch);
    k_deg2<<<(N_EDGES + 255) / 256, 256>>>();
    k_blocksum<<<NBLK, 256>>>();
    k_scanb<<<1, 256>>>();
    k_offsets<<<NBLK, 256>>>();
    k_fill<<<(N_EDGES + 255) / 256, 256>>>();
    k_transpose<<<(5 * HID * HID + 255) / 256, 256>>>(W_emb, W_layers);

    int gemm_blocks = (N_NODES + 63) / 64;
    float* d_h = nullptr;
    cudaGetSymbolAddress((void**)&d_h, g_h);
    const float* Wt = nullptr;
    cudaGetSymbolAddress((void**)&Wt, g_Wt);

    k_gemm<<<gemm_blocks, 256, GEMM_SMEM>>>(x, Wt, b_emb, 0);

    int gln_blocks = (N_NODES + 15) / 16;    // 3125
    for (int i = 0; i < 4; i++) {
        k_gemm<<<gemm_blocks, 256, GEMM_SMEM>>>(d_h, Wt + (1 + i) * HID * HID, nullptr, 1);
        k_gln<<<gln_blocks, 512>>>(b_layers + i * HID, ln_gamma + i * HID, ln_beta + i * HID,
                                   (i == 3) ? W_out : nullptr);
    }

    k_out<<<1, 32>>>(out);
}

// round 6
// speedup vs baseline: 3.0040x; 1.5673x over previous
#include <cuda_runtime.h>
#include <cstdint>

#define N_NODES 50000
#define N_EDGES 800000
#define HID     128
#define N_GRAPHS 32
#define LN_EPS  1e-5f
#define NBLK    196                       // ceil(50000/256)
#define MMA_BLOCKS ((N_NODES + 127) / 128)  // 391
#define SKW 68                            // smem row stride in u32 (136 bf16) -> conflict-free

typedef unsigned int u32;
typedef unsigned long long ull;

// ---------------- scratch (device globals; no allocations allowed) ----------------
__device__ float g_h[N_NODES * HID];
__device__ __align__(16) u32 g_tb[N_NODES * HID / 2];   // t' as bf16x2
__device__ __align__(16) u32 g_Whi[5 * HID * HID / 2];  // W bf16 hi, [o][k] pairs
__device__ __align__(16) u32 g_Wlo[5 * HID * HID / 2];  // W bf16 lo
__device__ float g_dis[N_NODES];
__device__ int   g_edeg[N_NODES];
__device__ int   g_off[N_NODES + 1];
__device__ int   g_cursor[N_NODES];
__device__ int   g_csr[N_EDGES];
__device__ int   g_row[N_EDGES];
__device__ int   g_col[N_EDGES];
__device__ int   g_batch[N_NODES];
__device__ int   g_bsum[NBLK];
__device__ int   g_bpre[NBLK];
__device__ float g_sums[N_GRAPHS];
__device__ int   g_cnts[N_GRAPHS];
__device__ int   g_flag64;

// ---------------- helpers ----------------
// cvt.rn.bf16x2.f32 d, a, b : d.hi = bf16(a), d.lo = bf16(b)
__device__ __forceinline__ u32 cvt2(float hi_elem, float lo_elem) {
    u32 r; asm("cvt.rn.bf16x2.f32 %0, %1, %2;" : "=r"(r) : "f"(hi_elem), "f"(lo_elem)); return r;
}
__device__ __forceinline__ float bf_lo(u32 v) { return __uint_as_float(v << 16); }
__device__ __forceinline__ float bf_hi(u32 v) { return __uint_as_float(v & 0xffff0000u); }

__device__ __forceinline__ void mma16816(float& c0, float& c1, float& c2, float& c3,
                                         u32 a0, u32 a1, u32 a2, u32 a3, u32 b0, u32 b1) {
    asm volatile(
        "mma.sync.aligned.m16n8k16.row.col.f32.bf16.bf16.f32 "
        "{%0,%1,%2,%3}, {%4,%5,%6,%7}, {%8,%9}, {%0,%1,%2,%3};"
        : "+f"(c0), "+f"(c1), "+f"(c2), "+f"(c3)
        : "r"(a0), "r"(a1), "r"(a2), "r"(a3), "r"(b0), "r"(b1));
}

// ---------------- detect dtype + zero accumulators ----------------
__global__ void __launch_bounds__(256) k_detect(const unsigned int* ei) {
    int i = blockIdx.x * 256 + threadIdx.x;
    if (i < N_NODES) g_edeg[i] = 0;
    if (i < N_GRAPHS) { g_sums[i] = 0.f; g_cnts[i] = 0; }
    if (blockIdx.x == 0 && threadIdx.x < 32) {
        int lane = threadIdx.x;
        unsigned ok = 1;
        #pragma unroll
        for (int j = 0; j < 4; j++) ok &= (ei[1 + 2 * (lane * 4 + j)] == 0u);
        unsigned all = __ballot_sync(0xffffffffu, ok != 0);
        if (lane == 0) g_flag64 = (all == 0xffffffffu);
    }
}

// convert indices + fused degree atomics (edeg pre-zeroed); load batch
__global__ void k_convert(const void* ei, const void* batch) {
    int i = blockIdx.x * blockDim.x + threadIdx.x;
    int f64 = g_flag64;
    if (i < N_EDGES) {
        int r, c;
        if (f64) {
            const long long* p = (const long long*)ei;
            r = (int)p[i]; c = (int)p[N_EDGES + i];
        } else {
            const int* p = (const int*)ei;
            r = p[i]; c = p[N_EDGES + i];
        }
        g_row[i] = r; g_col[i] = c;
        atomicAdd(&g_edeg[c], 1);
    }
    if (i < N_NODES) {
        int b = f64 ? (int)((const long long*)batch)[i] : ((const int*)batch)[i];
        g_batch[i] = b;
    }
}

// ---------------- parallel scan ----------------
__global__ void __launch_bounds__(256) k_blocksum() {
    __shared__ int ws[8];
    int v = blockIdx.x * 256 + threadIdx.x;
    int d = (v < N_NODES) ? g_edeg[v] : 0;
    int x = d;
    #pragma unroll
    for (int off = 1; off < 32; off <<= 1) {
        int y = __shfl_up_sync(0xffffffffu, x, off);
        if ((threadIdx.x & 31) >= off) x += y;
    }
    if ((threadIdx.x & 31) == 31) ws[threadIdx.x >> 5] = x;
    __syncthreads();
    if (threadIdx.x == 0) {
        int s = 0;
        #pragma unroll
        for (int i = 0; i < 8; i++) s += ws[i];
        g_bsum[blockIdx.x] = s;
    }
}

__global__ void __launch_bounds__(256) k_scanb() {
    __shared__ int ws[8];
    int tid = threadIdx.x;
    int d = (tid < NBLK) ? g_bsum[tid] : 0;
    int lane = tid & 31, wid = tid >> 5;
    int x = d;
    #pragma unroll
    for (int off = 1; off < 32; off <<= 1) {
        int y = __shfl_up_sync(0xffffffffu, x, off);
        if (lane >= off) x += y;
    }
    if (lane == 31) ws[wid] = x;
    __syncthreads();
    if (tid == 0) {
        int run = 0;
        #pragma unroll
        for (int i = 0; i < 8; i++) { int t = ws[i]; ws[i] = run; run += t; }
        g_off[N_NODES] = run;
    }
    __syncthreads();
    if (tid < NBLK) g_bpre[tid] = x - d + ws[wid];
}

__global__ void __launch_bounds__(256) k_offsets() {
    __shared__ int ws[8];
    int tid = threadIdx.x;
    int v = blockIdx.x * 256 + tid;
    int d = (v < N_NODES) ? g_edeg[v] : 0;
    int lane = tid & 31, wid = tid >> 5;
    int x = d;
    #pragma unroll
    for (int off = 1; off < 32; off <<= 1) {
        int y = __shfl_up_sync(0xffffffffu, x, off);
        if (lane >= off) x += y;
    }
    if (lane == 31) ws[wid] = x;
    __syncthreads();
    if (tid == 0) {
        int run = 0;
        #pragma unroll
        for (int i = 0; i < 8; i++) { int t = ws[i]; ws[i] = run; run += t; }
    }
    __syncthreads();
    if (v < N_NODES) {
        int excl = x - d + ws[wid] + g_bpre[blockIdx.x];
        g_off[v] = excl;
        g_cursor[v] = excl;
        g_dis[v] = rsqrtf((float)(d + 1));
    }
}

__global__ void k_fill() {
    int e = blockIdx.x * blockDim.x + threadIdx.x;
    if (e < N_EDGES) {
        int c = g_col[e];
        int pos = atomicAdd(&g_cursor[c], 1);
        g_csr[pos] = g_row[e];
    }
}

// ---- W prep: split W[o][k] fp32 -> bf16 hi/lo pairs, [o][k/2] u32, natural order ----
__global__ void k_wprep(const float* __restrict__ W_emb, const float* __restrict__ W_layers) {
    int i = blockIdx.x * blockDim.x + threadIdx.x;     // 5*128*32 float4 groups
    if (i >= 5 * 128 * 32) return;
    int w = i / (128 * 32), r = i % (128 * 32);
    const float* src = (w == 0) ? W_emb : (W_layers + (w - 1) * 16384);
    float4 a = ((const float4*)src)[r];
    u32 h0 = cvt2(a.y, a.x), h1 = cvt2(a.w, a.z);
    float l0 = a.x - bf_lo(h0), l1 = a.y - bf_hi(h0);
    float l2 = a.z - bf_lo(h1), l3 = a.w - bf_hi(h1);
    u32 q0 = cvt2(l1, l0), q1 = cvt2(l3, l2);
    int base = w * 8192 + r * 2;
    g_Whi[base] = h0; g_Whi[base + 1] = h1;
    g_Wlo[base] = q0; g_Wlo[base + 1] = q1;
}

// ---------------- tensor-core GEMM: out[n][o] = sum_k A[n][k]*W[o][k] ----------------
// mma.sync m16n8k16 bf16, 3-term split (AhWh + AhWl + AlWh), fp32 accum.
// Block: 128 rows x 128 cols, 256 threads. Warp (w&3)->rows 32w..., (w>>2)->cols 0/64.
// mode 0: g_h = .. + bias (fp32). mode 1: g_tb = bf16x2( dis[row] * .. ).
__global__ void __launch_bounds__(256) k_mma(const float* __restrict__ A,
                                             const u32* __restrict__ Whi,
                                             const u32* __restrict__ Wlo,
                                             const float* __restrict__ bias,
                                             int mode) {
    extern __shared__ u32 smu[];
    u32* sAhi = smu;
    u32* sAlo = smu + 128 * SKW;
    u32* sBhi = smu + 2 * 128 * SKW;
    u32* sBlo = smu + 3 * 128 * SKW;

    int tid = threadIdx.x;
    int row0 = blockIdx.x * 128;

    // stage A: fp32 -> bf16 hi/lo
    #pragma unroll
    for (int i = 0; i < 16; i++) {
        int f = tid + i * 256;                  // 4096 float4 over 128x128
        int r = f >> 5, c4 = f & 31;
        int gr = row0 + r;
        float4 a = (gr < N_NODES) ? ((const float4*)A)[gr * 32 + c4]
                                  : make_float4(0.f, 0.f, 0.f, 0.f);
        u32 h0 = cvt2(a.y, a.x), h1 = cvt2(a.w, a.z);
        float l0 = a.x - bf_lo(h0), l1 = a.y - bf_hi(h0);
        float l2 = a.z - bf_lo(h1), l3 = a.w - bf_hi(h1);
        u32 q0 = cvt2(l1, l0), q1 = cvt2(l3, l2);
        int idx = r * SKW + c4 * 2;
        sAhi[idx] = h0; sAhi[idx + 1] = h1;
        sAlo[idx] = q0; sAlo[idx + 1] = q1;
    }
    // stage W hi/lo (already bf16 pairs)
    #pragma unroll
    for (int i = 0; i < 16; i++) {
        int f = tid + i * 256;                  // 4096 uint2 over 128x64 u32
        int o = f >> 5, q = f & 31;
        uint2 vh = ((const uint2*)Whi)[f];
        uint2 vl = ((const uint2*)Wlo)[f];
        int idx = o * SKW + q * 2;
        sBhi[idx] = vh.x; sBhi[idx + 1] = vh.y;
        sBlo[idx] = vl.x; sBlo[idx + 1] = vl.y;
    }
    __syncthreads();

    int lane = tid & 31, warp = tid >> 5;
    int g = lane >> 2, tig = lane & 3;
    int wr = (warp & 3) * 32;          // warp row base (within tile)
    int wc = (warp >> 2) * 64;         // warp col base

    float acc[2][8][4];
    #pragma unroll
    for (int m = 0; m < 2; m++)
        #pragma unroll
        for (int n = 0; n < 8; n++)
            #pragma unroll
            for (int c = 0; c < 4; c++) acc[m][n][c] = 0.f;

    #pragma unroll
    for (int term = 0; term < 3; term++) {
        const u32* pa = (term == 2) ? sAlo : sAhi;
        const u32* pb = (term == 1) ? sBlo : sBhi;
        #pragma unroll
        for (int ks = 0; ks < 8; ks++) {
            int ko = ks * 8 + tig;              // u32 offset within row
            u32 a[2][4];
            #pragma unroll
            for (int m = 0; m < 2; m++) {
                int r = wr + m * 16 + g;
                a[m][0] = pa[r * SKW + ko];
                a[m][1] = pa[(r + 8) * SKW + ko];
                a[m][2] = pa[r * SKW + ko + 4];
                a[m][3] = pa[(r + 8) * SKW + ko + 4];
            }
            u32 b[8][2];
            #pragma unroll
            for (int n = 0; n < 8; n++) {
                int o = wc + n * 8 + g;
                b[n][0] = pb[o * SKW + ko];
                b[n][1] = pb[o * SKW + ko + 4];
            }
            #pragma unroll
            for (int m = 0; m < 2; m++)
                #pragma unroll
                for (int n = 0; n < 8; n++)
                    mma16816(acc[m][n][0], acc[m][n][1], acc[m][n][2], acc[m][n][3],
                             a[m][0], a[m][1], a[m][2], a[m][3], b[n][0], b[n][1]);
        }
    }

    // epilogue: direct stores (c0,c1 contiguous cols)
    #pragma unroll
    for (int m = 0; m < 2; m++) {
        int r0 = row0 + wr + m * 16 + g;
        int r1 = r0 + 8;
        bool ok0 = (r0 < N_NODES), ok1 = (r1 < N_NODES);
        if (mode == 0) {
            #pragma unroll
            for (int n = 0; n < 8; n++) {
                int col = wc + n * 8 + 2 * tig;
                float b0 = bias[col], b1 = bias[col + 1];
                if (ok0) *(float2*)(g_h + r0 * HID + col) =
                    make_float2(acc[m][n][0] + b0, acc[m][n][1] + b1);
                if (ok1) *(float2*)(g_h + r1 * HID + col) =
                    make_float2(acc[m][n][2] + b0, acc[m][n][3] + b1);
            }
        } else {
            float d0 = ok0 ? g_dis[r0] : 0.f;
            float d1 = ok1 ? g_dis[r1] : 0.f;
            #pragma unroll
            for (int n = 0; n < 8; n++) {
                int col = wc + n * 8 + 2 * tig;
                if (ok0) g_tb[r0 * 64 + col / 2] = cvt2(acc[m][n][1] * d0, acc[m][n][0] * d0);
                if (ok1) g_tb[r1 * 64 + col / 2] = cvt2(acc[m][n][3] * d1, acc[m][n][2] * d1);
            }
        }
    }
}

// ------- fused CSR gather (bf16 msgs) + residual + relu + LayerNorm (+pool) -------
__global__ void __launch_bounds__(512) k_gln(const float* __restrict__ b,
                                             const float* __restrict__ gamma,
                                             const float* __restrict__ beta,
                                             const float* __restrict__ Wout) {
    __shared__ float ssum[N_GRAPHS];
    __shared__ int   scnt[N_GRAPHS];
    const bool pool = (Wout != nullptr);
    int tid = threadIdx.x;
    if (pool) {
        if (tid < N_GRAPHS) { ssum[tid] = 0.f; scnt[tid] = 0; }
        __syncthreads();
    }

    int v = (blockIdx.x * blockDim.x + tid) >> 5;
    int lane = tid & 31;
    bool active = (v < N_NODES);
    float4 o = make_float4(0.f, 0.f, 0.f, 0.f);

    if (active) {
        const uint2* T = (const uint2*)g_tb;
        uint2 sv = T[v * 32 + lane];
        float a0 = bf_lo(sv.x), a1 = bf_hi(sv.x), a2 = bf_lo(sv.y), a3 = bf_hi(sv.y);

        int i = g_off[v], e = g_off[v + 1];
        for (; i + 4 <= e; i += 4) {
            int r0 = __ldg(&g_csr[i]);
            int r1 = __ldg(&g_csr[i + 1]);
            int r2 = __ldg(&g_csr[i + 2]);
            int r3 = __ldg(&g_csr[i + 3]);
            uint2 m0 = T[r0 * 32 + lane];
            uint2 m1 = T[r1 * 32 + lane];
            uint2 m2 = T[r2 * 32 + lane];
            uint2 m3 = T[r3 * 32 + lane];
            a0 += (bf_lo(m0.x) + bf_lo(m1.x)) + (bf_lo(m2.x) + bf_lo(m3.x));
            a1 += (bf_hi(m0.x) + bf_hi(m1.x)) + (bf_hi(m2.x) + bf_hi(m3.x));
            a2 += (bf_lo(m0.y) + bf_lo(m1.y)) + (bf_lo(m2.y) + bf_lo(m3.y));
            a3 += (bf_hi(m0.y) + bf_hi(m1.y)) + (bf_hi(m2.y) + bf_hi(m3.y));
        }
        for (; i < e; i++) {
            int r = __ldg(&g_csr[i]);
            uint2 m = T[r * 32 + lane];
            a0 += bf_lo(m.x); a1 += bf_hi(m.x); a2 += bf_lo(m.y); a3 += bf_hi(m.y);
        }

        float dv = g_dis[v];
        float4 hv = *(const float4*)(g_h + v * HID + lane * 4);
        float4 bv = ((const float4*)b)[lane];
        float x0 = hv.x + fmaxf(dv * a0 + bv.x, 0.f);
        float x1 = hv.y + fmaxf(dv * a1 + bv.y, 0.f);
        float x2 = hv.z + fmaxf(dv * a2 + bv.z, 0.f);
        float x3 = hv.w + fmaxf(dv * a3 + bv.w, 0.f);

        float s = x0 + x1 + x2 + x3;
        #pragma unroll
        for (int off = 16; off > 0; off >>= 1) s += __shfl_xor_sync(0xffffffffu, s, off);
        float mu = s * (1.f / 128.f);
        float d0 = x0 - mu, d1 = x1 - mu, d2 = x2 - mu, d3 = x3 - mu;
        float q = d0 * d0 + d1 * d1 + d2 * d2 + d3 * d3;
        #pragma unroll
        for (int off = 16; off > 0; off >>= 1) q += __shfl_xor_sync(0xffffffffu, q, off);
        float rs = rsqrtf(q * (1.f / 128.f) + LN_EPS);
        float4 gv = ((const float4*)gamma)[lane];
        float4 be = ((const float4*)beta)[lane];
        o.x = d0 * rs * gv.x + be.x;
        o.y = d1 * rs * gv.y + be.y;
        o.z = d2 * rs * gv.z + be.z;
        o.w = d3 * rs * gv.w + be.w;
        *(float4*)(g_h + v * HID + lane * 4) = o;
    }

    if (pool) {
        float s = 0.f;
        if (active) {
            float4 wv = ((const float4*)Wout)[lane];
            s = o.x * wv.x + o.y * wv.y + o.z * wv.z + o.w * wv.w;
        }
        #pragma unroll
        for (int off = 16; off > 0; off >>= 1) s += __shfl_xor_sync(0xffffffffu, s, off);
        if (active && lane == 0) {
            int bg = g_batch[v];
            atomicAdd(&ssum[bg], s);
            atomicAdd(&scnt[bg], 1);
        }
        __syncthreads();
        if (tid < N_GRAPHS && scnt[tid] > 0) {
            atomicAdd(&g_sums[tid], ssum[tid]);
            atomicAdd(&g_cnts[tid], scnt[tid]);
        }
    }
}

__global__ void k_out(float* out) {
    int g = threadIdx.x;
    if (g < N_GRAPHS) out[g] = g_sums[g] / fmaxf((float)g_cnts[g], 1.f);
}

// ---------------- launch ----------------
extern "C" void kernel_launch(void* const* d_in, const int* in_sizes, int n_in,
                              void* d_out, int out_size) {
    const float* x        = (const float*)d_in[0];
    const void*  ei       = d_in[1];
    const void*  batch    = d_in[2];
    const float* W_emb    = (const float*)d_in[3];
    const float* b_emb    = (const float*)d_in[4];
    const float* W_layers = (const float*)d_in[5];
    const float* b_layers = (const float*)d_in[6];
    const float* ln_gamma = (const float*)d_in[7];
    const float* ln_beta  = (const float*)d_in[8];
    const float* W_out    = (const float*)d_in[9];
    float* out = (float*)d_out;

    const int MMA_SMEM = 4 * 128 * SKW * sizeof(u32);   // 139,264 B
    static int smem_set = 0;
    if (!smem_set) {
        cudaFuncSetAttribute(k_mma, cudaFuncAttributeMaxDynamicSharedMemorySize, MMA_SMEM);
        smem_set = 1;
    }

    k_detect<<<NBLK, 256>>>((const unsigned int*)ei);
    k_convert<<<(N_EDGES + 255) / 256, 256>>>(ei, batch);
    k_blocksum<<<NBLK, 256>>>();
    k_scanb<<<1, 256>>>();
    k_offsets<<<NBLK, 256>>>();
    k_fill<<<(N_EDGES + 255) / 256, 256>>>();
    k_wprep<<<(5 * 128 * 32 + 255) / 256, 256>>>(W_emb, W_layers);

    float* d_h = nullptr;
    cudaGetSymbolAddress((void**)&d_h, g_h);
    u32* whi = nullptr;
    cudaGetSymbolAddress((void**)&whi, g_Whi);
    u32* wlo = nullptr;
    cudaGetSymbolAddress((void**)&wlo, g_Wlo);

    k_mma<<<MMA_BLOCKS, 256, MMA_SMEM>>>(x, whi, wlo, b_emb, 0);

    int gln_blocks = (N_NODES + 15) / 16;    // 3125
    for (int i = 0; i < 4; i++) {
        k_mma<<<MMA_BLOCKS, 256, MMA_SMEM>>>(d_h, whi + (1 + i) * 8192, wlo + (1 + i) * 8192,
                                             nullptr, 1);
        k_gln<<<gln_blocks, 512>>>(b_layers + i * HID, ln_gamma + i * HID, ln_beta + i * HID,
                                   (i == 3) ? W_out : nullptr);
    }

    k_out<<<1, 32>>>(out);
}

// round 7
// speedup vs baseline: 3.0267x; 1.0075x over previous
#include <cuda_runtime.h>
#include <cstdint>

#define N_NODES 50000
#define N_EDGES 800000
#define HID     128
#define N_GRAPHS 32
#define LN_EPS  1e-5f
#define NBLK    196                         // ceil(50000/256)
#define EBLK    3125                        // ceil(800000/256)
#define WPBLK   80                          // ceil(5*128*32/256)
#define MMA_BLOCKS ((N_NODES + 127) / 128)  // 391
#define SKW 68                              // smem row stride in u32 (272B, 16B-aligned rows)

typedef unsigned int u32;

// ---------------- scratch (device globals; zero-initialized at load) ----------------
__device__ float g_h[N_NODES * HID];
__device__ __align__(16) u32 g_tb[N_NODES * HID / 2];   // t' as bf16x2
__device__ __align__(16) u32 g_Whi[5 * HID * HID / 2];  // W bf16 hi, [o][k] pairs
__device__ __align__(16) u32 g_Wlo[5 * HID * HID / 2];  // W bf16 lo
__device__ float g_dis[N_NODES];
__device__ int   g_edeg[N_NODES];           // ZEROED at end of every launch (and at load)
__device__ int   g_off[N_NODES + 1];
__device__ int   g_cursor[N_NODES];
__device__ int   g_csr[N_EDGES];
__device__ int   g_row[N_EDGES];
__device__ int   g_col[N_EDGES];
__device__ int   g_batch[N_NODES];
__device__ int   g_bsum[NBLK];
__device__ float g_sums[N_GRAPHS];          // ZEROED at end of every launch
__device__ int   g_cnts[N_GRAPHS];          // ZEROED at end of every launch

// ---------------- helpers ----------------
__device__ __forceinline__ u32 cvt2(float hi_elem, float lo_elem) {
    u32 r; asm("cvt.rn.bf16x2.f32 %0, %1, %2;" : "=r"(r) : "f"(hi_elem), "f"(lo_elem)); return r;
}
__device__ __forceinline__ float bf_lo(u32 v) { return __uint_as_float(v << 16); }
__device__ __forceinline__ float bf_hi(u32 v) { return __uint_as_float(v & 0xffff0000u); }

__device__ __forceinline__ u32 smem_u32(const void* p) {
    u32 a;
    asm("{ .reg .u64 t; cvta.to.shared.u64 t, %1; cvt.u32.u64 %0, t; }" : "=r"(a) : "l"(p));
    return a;
}
__device__ __forceinline__ void ldm4(u32& r0, u32& r1, u32& r2, u32& r3, u32 addr) {
    asm volatile("ldmatrix.sync.aligned.m8n8.x4.shared.b16 {%0,%1,%2,%3}, [%4];"
                 : "=r"(r0), "=r"(r1), "=r"(r2), "=r"(r3) : "r"(addr));
}
__device__ __forceinline__ void mma16816(float& c0, float& c1, float& c2, float& c3,
                                         u32 a0, u32 a1, u32 a2, u32 a3, u32 b0, u32 b1) {
    asm volatile(
        "mma.sync.aligned.m16n8k16.row.col.f32.bf16.bf16.f32 "
        "{%0,%1,%2,%3}, {%4,%5,%6,%7}, {%8,%9}, {%0,%1,%2,%3};"
        : "+f"(c0), "+f"(c1), "+f"(c2), "+f"(c3)
        : "r"(a0), "r"(a1), "r"(a2), "r"(a3), "r"(b0), "r"(b1));
}

// ---- convert indices + fused dtype detect + degree atomics (edeg pre-zeroed) ----
__global__ void __launch_bounds__(256) k_convert(const void* ei, const void* batch) {
    __shared__ int sflag;
    if (threadIdx.x < 32) {
        const unsigned int* w = (const unsigned int*)ei;
        unsigned ok = 1;
        #pragma unroll
        for (int j = 0; j < 4; j++) ok &= (w[1 + 2 * (threadIdx.x * 4 + j)] == 0u);
        unsigned all = __ballot_sync(0xffffffffu, ok != 0);
        if (threadIdx.x == 0) sflag = (all == 0xffffffffu);
    }
    __syncthreads();
    int f64 = sflag;
    int i = blockIdx.x * 256 + threadIdx.x;
    if (i < N_EDGES) {
        int r, c;
        if (f64) {
            const long long* p = (const long long*)ei;
            r = (int)p[i]; c = (int)p[N_EDGES + i];
        } else {
            const int* p = (const int*)ei;
            r = p[i]; c = p[N_EDGES + i];
        }
        g_row[i] = r; g_col[i] = c;
        atomicAdd(&g_edeg[c], 1);
    }
    if (i < N_NODES) {
        int b = f64 ? (int)((const long long*)batch)[i] : ((const int*)batch)[i];
        g_batch[i] = b;
    }
}

// ---------------- scan phase 1: per-block sums ----------------
__global__ void __launch_bounds__(256) k_blocksum() {
    __shared__ int ws[8];
    int v = blockIdx.x * 256 + threadIdx.x;
    int d = (v < N_NODES) ? g_edeg[v] : 0;
    int x = d;
    #pragma unroll
    for (int off = 1; off < 32; off <<= 1) {
        int y = __shfl_up_sync(0xffffffffu, x, off);
        if ((threadIdx.x & 31) >= off) x += y;
    }
    if ((threadIdx.x & 31) == 31) ws[threadIdx.x >> 5] = x;
    __syncthreads();
    if (threadIdx.x == 0) {
        int s = 0;
        #pragma unroll
        for (int i = 0; i < 8; i++) s += ws[i];
        g_bsum[blockIdx.x] = s;
    }
}

// ---------------- scan phase 2: per-block prefix reduction + node offsets ----------------
__global__ void __launch_bounds__(256) k_offsets() {
    __shared__ int ws[8], ws2[8];
    __shared__ int spre, stot;
    int tid = threadIdx.x, lane = tid & 31, wid = tid >> 5;

    int bs = (tid < NBLK) ? g_bsum[tid] : 0;
    int mpre = (tid < (int)blockIdx.x) ? bs : 0;
    int mtot = bs;
    #pragma unroll
    for (int off = 16; off > 0; off >>= 1) {
        mpre += __shfl_xor_sync(0xffffffffu, mpre, off);
        mtot += __shfl_xor_sync(0xffffffffu, mtot, off);
    }
    if (lane == 0) { ws[wid] = mpre; ws2[wid] = mtot; }
    __syncthreads();
    if (tid == 0) {
        int a = 0, t = 0;
        #pragma unroll
        for (int i = 0; i < 8; i++) { a += ws[i]; t += ws2[i]; }
        spre = a; stot = t;
    }
    __syncthreads();
    if (blockIdx.x == NBLK - 1 && tid == 0) g_off[N_NODES] = stot;

    int v = blockIdx.x * 256 + tid;
    int d = (v < N_NODES) ? g_edeg[v] : 0;
    int x = d;
    #pragma unroll
    for (int off = 1; off < 32; off <<= 1) {
        int y = __shfl_up_sync(0xffffffffu, x, off);
        if (lane >= off) x += y;
    }
    __syncthreads();                    // all reads of ws/spre done
    if (lane == 31) ws[wid] = x;
    __syncthreads();
    if (tid == 0) {
        int run = 0;
        #pragma unroll
        for (int i = 0; i < 8; i++) { int t = ws[i]; ws[i] = run; run += t; }
    }
    __syncthreads();
    if (v < N_NODES) {
        int excl = x - d + ws[wid] + spre;
        g_off[v] = excl;
        g_cursor[v] = excl;
        g_dis[v] = rsqrtf((float)(d + 1));
    }
}

// ---- fill CSR + W prep (fused; wprep rides extra grid slice) ----
__global__ void __launch_bounds__(256) k_fillprep(const float* __restrict__ W_emb,
                                                  const float* __restrict__ W_layers) {
    if ((int)blockIdx.x < EBLK) {
        int e = blockIdx.x * 256 + threadIdx.x;
        if (e < N_EDGES) {
            int c = g_col[e];
            int pos = atomicAdd(&g_cursor[c], 1);
            g_csr[pos] = g_row[e];
        }
    } else {
        int i = (blockIdx.x - EBLK) * 256 + threadIdx.x;
        if (i < 5 * 128 * 32) {
            int w = i / (128 * 32), r = i % (128 * 32);
            const float* src = (w == 0) ? W_emb : (W_layers + (w - 1) * 16384);
            float4 a = ((const float4*)src)[r];
            u32 h0 = cvt2(a.y, a.x), h1 = cvt2(a.w, a.z);
            float l0 = a.x - bf_lo(h0), l1 = a.y - bf_hi(h0);
            float l2 = a.z - bf_lo(h1), l3 = a.w - bf_hi(h1);
            u32 q0 = cvt2(l1, l0), q1 = cvt2(l3, l2);
            int base = w * 8192 + r * 2;
            g_Whi[base] = h0; g_Whi[base + 1] = h1;
            g_Wlo[base] = q0; g_Wlo[base + 1] = q1;
        }
    }
}

// ---------------- tensor-core GEMM via mma.sync + ldmatrix ----------------
// out[n][o] = sum_k A[n][k]*W[o][k]; 3-term bf16 split, fp32 accum.
// Block 128x128, 256 thr. Warp (w&3)->row 32w, (w>>2)->col 0/64.
// mode 0: g_h = ..+bias; mode 1: g_tb = bf16x2(dis[row]*..)
__global__ void __launch_bounds__(256) k_mma(const float* __restrict__ A,
                                             const u32* __restrict__ Whi,
                                             const u32* __restrict__ Wlo,
                                             const float* __restrict__ bias,
                                             int mode) {
    extern __shared__ u32 smu[];
    u32* sAhi = smu;
    u32* sAlo = smu + 128 * SKW;
    u32* sBhi = smu + 2 * 128 * SKW;
    u32* sBlo = smu + 3 * 128 * SKW;

    int tid = threadIdx.x;
    int row0 = blockIdx.x * 128;

    #pragma unroll
    for (int i = 0; i < 16; i++) {
        int f = tid + i * 256;
        int r = f >> 5, c4 = f & 31;
        int gr = row0 + r;
        float4 a = (gr < N_NODES) ? ((const float4*)A)[gr * 32 + c4]
                                  : make_float4(0.f, 0.f, 0.f, 0.f);
        u32 h0 = cvt2(a.y, a.x), h1 = cvt2(a.w, a.z);
        float l0 = a.x - bf_lo(h0), l1 = a.y - bf_hi(h0);
        float l2 = a.z - bf_lo(h1), l3 = a.w - bf_hi(h1);
        u32 q0 = cvt2(l1, l0), q1 = cvt2(l3, l2);
        int idx = r * SKW + c4 * 2;
        sAhi[idx] = h0; sAhi[idx + 1] = h1;
        sAlo[idx] = q0; sAlo[idx + 1] = q1;
    }
    #pragma unroll
    for (int i = 0; i < 16; i++) {
        int f = tid + i * 256;
        int o = f >> 5, q = f & 31;
        uint2 vh = ((const uint2*)Whi)[f];
        uint2 vl = ((const uint2*)Wlo)[f];
        int idx = o * SKW + q * 2;
        sBhi[idx] = vh.x; sBhi[idx + 1] = vh.y;
        sBlo[idx] = vl.x; sBlo[idx + 1] = vl.y;
    }
    __syncthreads();

    int lane = tid & 31, warp = tid >> 5;
    int g = lane >> 2, tig = lane & 3;
    int wr = (warp & 3) * 32;
    int wc = (warp >> 2) * 64;

    u32 base = smem_u32(smu);
    // per-thread ldmatrix row byte offsets (within a buffer)
    u32 aoff0 = (u32)((wr + (lane & 15)) * (SKW * 4) + ((lane >> 4) * 16));
    u32 aoff1 = aoff0 + 16 * (SKW * 4);
    u32 boff[4];
    #pragma unroll
    for (int np = 0; np < 4; np++) {
        int orow = wc + np * 16 + (lane & 7) + ((lane >> 4) & 1) * 8;
        boff[np] = (u32)(orow * (SKW * 4) + (((lane >> 3) & 1) * 16));
    }
    const u32 OF_AHI = 0, OF_ALO = 128 * SKW * 4;
    const u32 OF_BHI = 2 * 128 * SKW * 4, OF_BLO = 3 * 128 * SKW * 4;

    float acc[2][8][4];
    #pragma unroll
    for (int m = 0; m < 2; m++)
        #pragma unroll
        for (int n = 0; n < 8; n++)
            #pragma unroll
            for (int c = 0; c < 4; c++) acc[m][n][c] = 0.f;

    #pragma unroll
    for (int term = 0; term < 3; term++) {
        u32 pa = base + ((term == 2) ? OF_ALO : OF_AHI);
        u32 pb = base + ((term == 1) ? OF_BLO : OF_BHI);
        #pragma unroll
        for (int ks = 0; ks < 8; ks++) {
            u32 kb = ks * 32;
            u32 a[2][4];
            ldm4(a[0][0], a[0][1], a[0][2], a[0][3], pa + aoff0 + kb);
            ldm4(a[1][0], a[1][1], a[1][2], a[1][3], pa + aoff1 + kb);
            u32 b[4][4];
            #pragma unroll
            for (int np = 0; np < 4; np++)
                ldm4(b[np][0], b[np][1], b[np][2], b[np][3], pb + boff[np] + kb);
            #pragma unroll
            for (int m = 0; m < 2; m++)
                #pragma unroll
                for (int np = 0; np < 4; np++) {
                    mma16816(acc[m][2 * np][0], acc[m][2 * np][1], acc[m][2 * np][2], acc[m][2 * np][3],
                             a[m][0], a[m][1], a[m][2], a[m][3], b[np][0], b[np][1]);
                    mma16816(acc[m][2 * np + 1][0], acc[m][2 * np + 1][1], acc[m][2 * np + 1][2], acc[m][2 * np + 1][3],
                             a[m][0], a[m][1], a[m][2], a[m][3], b[np][2], b[np][3]);
                }
        }
    }

    #pragma unroll
    for (int m = 0; m < 2; m++) {
        int r0 = row0 + wr + m * 16 + g;
        int r1 = r0 + 8;
        bool ok0 = (r0 < N_NODES), ok1 = (r1 < N_NODES);
        if (mode == 0) {
            #pragma unroll
            for (int n = 0; n < 8; n++) {
                int col = wc + n * 8 + 2 * tig;
                float b0 = bias[col], b1 = bias[col + 1];
                if (ok0) *(float2*)(g_h + r0 * HID + col) =
                    make_float2(acc[m][n][0] + b0, acc[m][n][1] + b1);
                if (ok1) *(float2*)(g_h + r1 * HID + col) =
                    make_float2(acc[m][n][2] + b0, acc[m][n][3] + b1);
            }
        } else {
            float d0 = ok0 ? g_dis[r0] : 0.f;
            float d1 = ok1 ? g_dis[r1] : 0.f;
            #pragma unroll
            for (int n = 0; n < 8; n++) {
                int col = wc + n * 8 + 2 * tig;
                if (ok0) g_tb[r0 * 64 + col / 2] = cvt2(acc[m][n][1] * d0, acc[m][n][0] * d0);
                if (ok1) g_tb[r1 * 64 + col / 2] = cvt2(acc[m][n][3] * d1, acc[m][n][2] * d1);
            }
        }
    }
}

// ------- fused CSR gather (bf16 msgs) + residual + relu + LayerNorm (+pool) -------
__global__ void __launch_bounds__(512) k_gln(const float* __restrict__ b,
                                             const float* __restrict__ gamma,
                                             const float* __restrict__ beta,
                                             const float* __restrict__ Wout) {
    __shared__ float ssum[N_GRAPHS];
    __shared__ int   scnt[N_GRAPHS];
    const bool pool = (Wout != nullptr);
    int tid = threadIdx.x;
    if (pool) {
        if (tid < N_GRAPHS) { ssum[tid] = 0.f; scnt[tid] = 0; }
        __syncthreads();
    }

    int v = (blockIdx.x * blockDim.x + tid) >> 5;
    int lane = tid & 31;
    bool active = (v < N_NODES);
    float4 o = make_float4(0.f, 0.f, 0.f, 0.f);

    if (active) {
        const uint2* T = (const uint2*)g_tb;
        uint2 sv = T[v * 32 + lane];
        float a0 = bf_lo(sv.x), a1 = bf_hi(sv.x), a2 = bf_lo(sv.y), a3 = bf_hi(sv.y);

        int i = g_off[v], e = g_off[v + 1];
        for (; i + 4 <= e; i += 4) {
            int r0 = __ldg(&g_csr[i]);
            int r1 = __ldg(&g_csr[i + 1]);
            int r2 = __ldg(&g_csr[i + 2]);
            int r3 = __ldg(&g_csr[i + 3]);
            uint2 m0 = T[r0 * 32 + lane];
            uint2 m1 = T[r1 * 32 + lane];
            uint2 m2 = T[r2 * 32 + lane];
            uint2 m3 = T[r3 * 32 + lane];
            a0 += (bf_lo(m0.x) + bf_lo(m1.x)) + (bf_lo(m2.x) + bf_lo(m3.x));
            a1 += (bf_hi(m0.x) + bf_hi(m1.x)) + (bf_hi(m2.x) + bf_hi(m3.x));
            a2 += (bf_lo(m0.y) + bf_lo(m1.y)) + (bf_lo(m2.y) + bf_lo(m3.y));
            a3 += (bf_hi(m0.y) + bf_hi(m1.y)) + (bf_hi(m2.y) + bf_hi(m3.y));
        }
        for (; i < e; i++) {
            int r = __ldg(&g_csr[i]);
            uint2 m = T[r * 32 + lane];
            a0 += bf_lo(m.x); a1 += bf_hi(m.x); a2 += bf_lo(m.y); a3 += bf_hi(m.y);
        }

        float dv = g_dis[v];
        float4 hv = *(const float4*)(g_h + v * HID + lane * 4);
        float4 bv = ((const float4*)b)[lane];
        float x0 = hv.x + fmaxf(dv * a0 + bv.x, 0.f);
        float x1 = hv.y + fmaxf(dv * a1 + bv.y, 0.f);
        float x2 = hv.z + fmaxf(dv * a2 + bv.z, 0.f);
        float x3 = hv.w + fmaxf(dv * a3 + bv.w, 0.f);

        float s = x0 + x1 + x2 + x3;
        #pragma unroll
        for (int off = 16; off > 0; off >>= 1) s += __shfl_xor_sync(0xffffffffu, s, off);
        float mu = s * (1.f / 128.f);
        float d0 = x0 - mu, d1 = x1 - mu, d2 = x2 - mu, d3 = x3 - mu;
        float q = d0 * d0 + d1 * d1 + d2 * d2 + d3 * d3;
        #pragma unroll
        for (int off = 16; off > 0; off >>= 1) q += __shfl_xor_sync(0xffffffffu, q, off);
        float rs = rsqrtf(q * (1.f / 128.f) + LN_EPS);
        float4 gv = ((const float4*)gamma)[lane];
        float4 be = ((const float4*)beta)[lane];
        o.x = d0 * rs * gv.x + be.x;
        o.y = d1 * rs * gv.y + be.y;
        o.z = d2 * rs * gv.z + be.z;
        o.w = d3 * rs * gv.w + be.w;
        *(float4*)(g_h + v * HID + lane * 4) = o;
    }

    if (pool) {
        float s = 0.f;
        if (active) {
            float4 wv = ((const float4*)Wout)[lane];
            s = o.x * wv.x + o.y * wv.y + o.z * wv.z + o.w * wv.w;
        }
        #pragma unroll
        for (int off = 16; off > 0; off >>= 1) s += __shfl_xor_sync(0xffffffffu, s, off);
        if (active && lane == 0) {
            int bg = g_batch[v];
            atomicAdd(&ssum[bg], s);
            atomicAdd(&scnt[bg], 1);
        }
        __syncthreads();
        if (tid < N_GRAPHS && scnt[tid] > 0) {
            atomicAdd(&g_sums[tid], ssum[tid]);
            atomicAdd(&g_cnts[tid], scnt[tid]);
        }
    }
}

// ---- output + state re-zero (leaves edeg/sums/cnts zeroed for next launch) ----
__global__ void __launch_bounds__(256) k_out(float* out) {
    int i = blockIdx.x * 256 + threadIdx.x;
    if (blockIdx.x == 0 && threadIdx.x < N_GRAPHS) {
        int g = threadIdx.x;
        out[g] = g_sums[g] / fmaxf((float)g_cnts[g], 1.f);
        g_sums[g] = 0.f;
        g_cnts[g] = 0;
    }
    if (i < N_NODES) g_edeg[i] = 0;
}

// ---------------- launch ----------------
extern "C" void kernel_launch(void* const* d_in, const int* in_sizes, int n_in,
                              void* d_out, int out_size) {
    const float* x        = (const float*)d_in[0];
    const void*  ei       = d_in[1];
    const void*  batch    = d_in[2];
    const float* W_emb    = (const float*)d_in[3];
    const float* b_emb    = (const float*)d_in[4];
    const float* W_layers = (const float*)d_in[5];
    const float* b_layers = (const float*)d_in[6];
    const float* ln_gamma = (const float*)d_in[7];
    const float* ln_beta  = (const float*)d_in[8];
    const float* W_out    = (const float*)d_in[9];
    float* out = (float*)d_out;

    const int MMA_SMEM = 4 * 128 * SKW * sizeof(u32);   // 139,264 B
    static int smem_set = 0;
    if (!smem_set) {
        cudaFuncSetAttribute(k_mma, cudaFuncAttributeMaxDynamicSharedMemorySize, MMA_SMEM);
        smem_set = 1;
    }

    k_convert<<<EBLK, 256>>>(ei, batch);
    k_blocksum<<<NBLK, 256>>>();
    k_offsets<<<NBLK, 256>>>();
    k_fillprep<<<EBLK + WPBLK, 256>>>(W_emb, W_layers);

    float* d_h = nullptr;
    cudaGetSymbolAddress((void**)&d_h, g_h);
    u32* whi = nullptr;
    cudaGetSymbolAddress((void**)&whi, g_Whi);
    u32* wlo = nullptr;
    cudaGetSymbolAddress((void**)&wlo, g_Wlo);

    k_mma<<<MMA_BLOCKS, 256, MMA_SMEM>>>(x, whi, wlo, b_emb, 0);

    int gln_blocks = (N_NODES + 15) / 16;    // 3125
    for (int i = 0; i < 4; i++) {
        k_mma<<<MMA_BLOCKS, 256, MMA_SMEM>>>(d_h, whi + (1 + i) * 8192, wlo + (1 + i) * 8192,
                                             nullptr, 1);
        k_gln<<<gln_blocks, 512>>>(b_layers + i * HID, ln_gamma + i * HID, ln_beta + i * HID,
                                   (i == 3) ? W_out : nullptr);
    }

    k_out<<<NBLK, 256>>>(out);
}

// round 8
// speedup vs baseline: 3.3292x; 1.1000x over previous
#include <cuda_runtime.h>
#include <cstdint>

#define N_NODES 50000
#define N_EDGES 800000
#define HID     128
#define N_GRAPHS 32
#define LN_EPS  1e-5f
#define NBLK    196                         // ceil(50000/256)
#define EBLK    3125                        // ceil(800000/256)
#define WPBLK   80                          // ceil(5*128*32/256)
#define MMA_BLOCKS ((N_NODES + 127) / 128)  // 391
#define SKW 68                              // smem row stride in u32 (272B)

typedef unsigned int u32;

// ---------------- scratch (device globals; zero-initialized at load) ----------------
__device__ float g_h[N_NODES * HID];
__device__ __align__(16) u32 g_tb[N_NODES * HID / 2];   // t' as bf16x2
__device__ __align__(16) u32 g_Whi[5 * HID * HID / 2];  // W bf16 hi, [o][k] pairs
__device__ __align__(16) u32 g_Wlo[5 * HID * HID / 2];  // W bf16 lo
__device__ float g_dis[N_NODES];
__device__ int   g_edeg[N_NODES];           // ZEROED at end of every launch (and at load)
__device__ int   g_off[N_NODES + 1];
__device__ int   g_cursor[N_NODES];
__device__ int   g_csr[N_EDGES];
__device__ int   g_row[N_EDGES];
__device__ int   g_col[N_EDGES];
__device__ int   g_batch[N_NODES];
__device__ int   g_bsum[NBLK];
__device__ float g_sums[N_GRAPHS];          // ZEROED at end of every launch
__device__ int   g_cnts[N_GRAPHS];          // ZEROED at end of every launch

// ---------------- helpers ----------------
__device__ __forceinline__ u32 cvt2(float hi_elem, float lo_elem) {
    u32 r; asm("cvt.rn.bf16x2.f32 %0, %1, %2;" : "=r"(r) : "f"(hi_elem), "f"(lo_elem)); return r;
}
__device__ __forceinline__ float bf_lo(u32 v) { return __uint_as_float(v << 16); }
__device__ __forceinline__ float bf_hi(u32 v) { return __uint_as_float(v & 0xffff0000u); }

__device__ __forceinline__ u32 smem_u32(const void* p) {
    u32 a;
    asm("{ .reg .u64 t; cvta.to.shared.u64 t, %1; cvt.u32.u64 %0, t; }" : "=r"(a) : "l"(p));
    return a;
}
__device__ __forceinline__ void ldm4(u32& r0, u32& r1, u32& r2, u32& r3, u32 addr) {
    asm volatile("ldmatrix.sync.aligned.m8n8.x4.shared.b16 {%0,%1,%2,%3}, [%4];"
                 : "=r"(r0), "=r"(r1), "=r"(r2), "=r"(r3) : "r"(addr));
}
__device__ __forceinline__ void mma16816(float& c0, float& c1, float& c2, float& c3,
                                         u32 a0, u32 a1, u32 a2, u32 a3, u32 b0, u32 b1) {
    asm volatile(
        "mma.sync.aligned.m16n8k16.row.col.f32.bf16.bf16.f32 "
        "{%0,%1,%2,%3}, {%4,%5,%6,%7}, {%8,%9}, {%0,%1,%2,%3};"
        : "+f"(c0), "+f"(c1), "+f"(c2), "+f"(c3)
        : "r"(a0), "r"(a1), "r"(a2), "r"(a3), "r"(b0), "r"(b1));
}

// ---- convert indices + fused dtype detect + degree atomics (edeg pre-zeroed) ----
__global__ void __launch_bounds__(256) k_convert(const void* ei, const void* batch) {
    __shared__ int sflag;
    if (threadIdx.x < 32) {
        const unsigned int* w = (const unsigned int*)ei;
        unsigned ok = 1;
        #pragma unroll
        for (int j = 0; j < 4; j++) ok &= (w[1 + 2 * (threadIdx.x * 4 + j)] == 0u);
        unsigned all = __ballot_sync(0xffffffffu, ok != 0);
        if (threadIdx.x == 0) sflag = (all == 0xffffffffu);
    }
    __syncthreads();
    int f64 = sflag;
    int i = blockIdx.x * 256 + threadIdx.x;
    if (i < N_EDGES) {
        int r, c;
        if (f64) {
            const long long* p = (const long long*)ei;
            r = (int)p[i]; c = (int)p[N_EDGES + i];
        } else {
            const int* p = (const int*)ei;
            r = p[i]; c = p[N_EDGES + i];
        }
        g_row[i] = r; g_col[i] = c;
        atomicAdd(&g_edeg[c], 1);
    }
    if (i < N_NODES) {
        int b = f64 ? (int)((const long long*)batch)[i] : ((const int*)batch)[i];
        g_batch[i] = b;
    }
}

// ---------------- scan phase 1: per-block sums ----------------
__global__ void __launch_bounds__(256) k_blocksum() {
    __shared__ int ws[8];
    int v = blockIdx.x * 256 + threadIdx.x;
    int d = (v < N_NODES) ? g_edeg[v] : 0;
    int x = d;
    #pragma unroll
    for (int off = 1; off < 32; off <<= 1) {
        int y = __shfl_up_sync(0xffffffffu, x, off);
        if ((threadIdx.x & 31) >= off) x += y;
    }
    if ((threadIdx.x & 31) == 31) ws[threadIdx.x >> 5] = x;
    __syncthreads();
    if (threadIdx.x == 0) {
        int s = 0;
        #pragma unroll
        for (int i = 0; i < 8; i++) s += ws[i];
        g_bsum[blockIdx.x] = s;
    }
}

// ---------------- scan phase 2: per-block prefix + node offsets ----------------
__global__ void __launch_bounds__(256) k_offsets() {
    __shared__ int ws[8], ws2[8];
    __shared__ int spre, stot;
    int tid = threadIdx.x, lane = tid & 31, wid = tid >> 5;

    int bs = (tid < NBLK) ? g_bsum[tid] : 0;
    int mpre = (tid < (int)blockIdx.x) ? bs : 0;
    int mtot = bs;
    #pragma unroll
    for (int off = 16; off > 0; off >>= 1) {
        mpre += __shfl_xor_sync(0xffffffffu, mpre, off);
        mtot += __shfl_xor_sync(0xffffffffu, mtot, off);
    }
    if (lane == 0) { ws[wid] = mpre; ws2[wid] = mtot; }
    __syncthreads();
    if (tid == 0) {
        int a = 0, t = 0;
        #pragma unroll
        for (int i = 0; i < 8; i++) { a += ws[i]; t += ws2[i]; }
        spre = a; stot = t;
    }
    __syncthreads();
    if (blockIdx.x == NBLK - 1 && tid == 0) g_off[N_NODES] = stot;

    int v = blockIdx.x * 256 + tid;
    int d = (v < N_NODES) ? g_edeg[v] : 0;
    int x = d;
    #pragma unroll
    for (int off = 1; off < 32; off <<= 1) {
        int y = __shfl_up_sync(0xffffffffu, x, off);
        if (lane >= off) x += y;
    }
    __syncthreads();
    if (lane == 31) ws[wid] = x;
    __syncthreads();
    if (tid == 0) {
        int run = 0;
        #pragma unroll
        for (int i = 0; i < 8; i++) { int t = ws[i]; ws[i] = run; run += t; }
    }
    __syncthreads();
    if (v < N_NODES) {
        int excl = x - d + ws[wid] + spre;
        g_off[v] = excl;
        g_cursor[v] = excl;
        g_dis[v] = rsqrtf((float)(d + 1));
    }
}

// ---- fill CSR ----
__global__ void __launch_bounds__(256) k_fill() {
    int e = blockIdx.x * 256 + threadIdx.x;
    if (e < N_EDGES) {
        int c = g_col[e];
        int pos = atomicAdd(&g_cursor[c], 1);
        g_csr[pos] = g_row[e];
    }
}

// ---- W prep (runs on side stream) ----
__global__ void __launch_bounds__(256) k_wprep(const float* __restrict__ W_emb,
                                               const float* __restrict__ W_layers) {
    int i = blockIdx.x * 256 + threadIdx.x;
    if (i >= 5 * 128 * 32) return;
    int w = i / (128 * 32), r = i % (128 * 32);
    const float* src = (w == 0) ? W_emb : (W_layers + (w - 1) * 16384);
    float4 a = ((const float4*)src)[r];
    u32 h0 = cvt2(a.y, a.x), h1 = cvt2(a.w, a.z);
    float l0 = a.x - bf_lo(h0), l1 = a.y - bf_hi(h0);
    float l2 = a.z - bf_lo(h1), l3 = a.w - bf_hi(h1);
    u32 q0 = cvt2(l1, l0), q1 = cvt2(l3, l2);
    int base = w * 8192 + r * 2;
    g_Whi[base] = h0; g_Whi[base + 1] = h1;
    g_Wlo[base] = q0; g_Wlo[base + 1] = q1;
}

// ---------------- tensor-core GEMM via mma.sync + ldmatrix ----------------
// out[n][o] = sum_k A[n][k]*W[o][k]; 2-term split: Ah*(Whi + Wlo), fp32 accum.
// Block 128x128, 256 thr, 2 CTAs/SM (102KB smem).
// mode 0: g_h = ..+bias; mode 1: g_tb = bf16x2(dis[row]*..)
__global__ void __launch_bounds__(256, 2) k_mma(const float* __restrict__ A,
                                                const u32* __restrict__ Whi,
                                                const u32* __restrict__ Wlo,
                                                const float* __restrict__ bias,
                                                int mode) {
    extern __shared__ u32 smu[];
    u32* sAhi = smu;
    u32* sBhi = smu + 128 * SKW;
    u32* sBlo = smu + 2 * 128 * SKW;

    int tid = threadIdx.x;
    int row0 = blockIdx.x * 128;

    // stage A (hi only)
    #pragma unroll
    for (int i = 0; i < 16; i++) {
        int f = tid + i * 256;
        int r = f >> 5, c4 = f & 31;
        int gr = row0 + r;
        float4 a = (gr < N_NODES) ? ((const float4*)A)[gr * 32 + c4]
                                  : make_float4(0.f, 0.f, 0.f, 0.f);
        int idx = r * SKW + c4 * 2;
        sAhi[idx]     = cvt2(a.y, a.x);
        sAhi[idx + 1] = cvt2(a.w, a.z);
    }
    // stage W hi/lo
    #pragma unroll
    for (int i = 0; i < 16; i++) {
        int f = tid + i * 256;
        int o = f >> 5, q = f & 31;
        uint2 vh = ((const uint2*)Whi)[f];
        uint2 vl = ((const uint2*)Wlo)[f];
        int idx = o * SKW + q * 2;
        sBhi[idx] = vh.x; sBhi[idx + 1] = vh.y;
        sBlo[idx] = vl.x; sBlo[idx + 1] = vl.y;
    }
    __syncthreads();

    int lane = tid & 31, warp = tid >> 5;
    int g = lane >> 2, tig = lane & 3;
    int wr = (warp & 3) * 32;
    int wc = (warp >> 2) * 64;

    u32 base = smem_u32(smu);
    u32 aoff0 = (u32)((wr + (lane & 15)) * (SKW * 4) + ((lane >> 4) * 16));
    u32 aoff1 = aoff0 + 16 * (SKW * 4);
    u32 boff[4];
    #pragma unroll
    for (int np = 0; np < 4; np++) {
        int orow = wc + np * 16 + (lane & 7) + ((lane >> 4) & 1) * 8;
        boff[np] = (u32)(orow * (SKW * 4) + (((lane >> 3) & 1) * 16));
    }
    const u32 OF_BHI = 128 * SKW * 4, OF_BLO = 2 * 128 * SKW * 4;

    float acc[2][8][4];
    #pragma unroll
    for (int m = 0; m < 2; m++)
        #pragma unroll
        for (int n = 0; n < 8; n++)
            #pragma unroll
            for (int c = 0; c < 4; c++) acc[m][n][c] = 0.f;

    #pragma unroll
    for (int ks = 0; ks < 8; ks++) {
        u32 kb = ks * 32;
        u32 a[2][4];
        ldm4(a[0][0], a[0][1], a[0][2], a[0][3], base + aoff0 + kb);
        ldm4(a[1][0], a[1][1], a[1][2], a[1][3], base + aoff1 + kb);
        u32 bh[4][4], bl[4][4];
        #pragma unroll
        for (int np = 0; np < 4; np++) {
            ldm4(bh[np][0], bh[np][1], bh[np][2], bh[np][3], base + OF_BHI + boff[np] + kb);
            ldm4(bl[np][0], bl[np][1], bl[np][2], bl[np][3], base + OF_BLO + boff[np] + kb);
        }
        #pragma unroll
        for (int m = 0; m < 2; m++)
            #pragma unroll
            for (int np = 0; np < 4; np++) {
                mma16816(acc[m][2*np][0], acc[m][2*np][1], acc[m][2*np][2], acc[m][2*np][3],
                         a[m][0], a[m][1], a[m][2], a[m][3], bh[np][0], bh[np][1]);
                mma16816(acc[m][2*np+1][0], acc[m][2*np+1][1], acc[m][2*np+1][2], acc[m][2*np+1][3],
                         a[m][0], a[m][1], a[m][2], a[m][3], bh[np][2], bh[np][3]);
                mma16816(acc[m][2*np][0], acc[m][2*np][1], acc[m][2*np][2], acc[m][2*np][3],
                         a[m][0], a[m][1], a[m][2], a[m][3], bl[np][0], bl[np][1]);
                mma16816(acc[m][2*np+1][0], acc[m][2*np+1][1], acc[m][2*np+1][2], acc[m][2*np+1][3],
                         a[m][0], a[m][1], a[m][2], a[m][3], bl[np][2], bl[np][3]);
            }
    }

    #pragma unroll
    for (int m = 0; m < 2; m++) {
        int r0 = row0 + wr + m * 16 + g;
        int r1 = r0 + 8;
        bool ok0 = (r0 < N_NODES), ok1 = (r1 < N_NODES);
        if (mode == 0) {
            #pragma unroll
            for (int n = 0; n < 8; n++) {
                int col = wc + n * 8 + 2 * tig;
                float b0 = bias[col], b1 = bias[col + 1];
                if (ok0) *(float2*)(g_h + r0 * HID + col) =
                    make_float2(acc[m][n][0] + b0, acc[m][n][1] + b1);
                if (ok1) *(float2*)(g_h + r1 * HID + col) =
                    make_float2(acc[m][n][2] + b0, acc[m][n][3] + b1);
            }
        } else {
            float d0 = ok0 ? g_dis[r0] : 0.f;
            float d1 = ok1 ? g_dis[r1] : 0.f;
            #pragma unroll
            for (int n = 0; n < 8; n++) {
                int col = wc + n * 8 + 2 * tig;
                if (ok0) g_tb[r0 * 64 + col / 2] = cvt2(acc[m][n][1] * d0, acc[m][n][0] * d0);
                if (ok1) g_tb[r1 * 64 + col / 2] = cvt2(acc[m][n][3] * d1, acc[m][n][2] * d1);
            }
        }
    }
}

// ------- fused CSR gather (bf16 msgs) + residual + relu + LayerNorm (+pool) -------
__global__ void __launch_bounds__(512) k_gln(const float* __restrict__ b,
                                             const float* __restrict__ gamma,
                                             const float* __restrict__ beta,
                                             const float* __restrict__ Wout) {
    __shared__ float ssum[N_GRAPHS];
    __shared__ int   scnt[N_GRAPHS];
    const bool pool = (Wout != nullptr);
    int tid = threadIdx.x;
    if (pool) {
        if (tid < N_GRAPHS) { ssum[tid] = 0.f; scnt[tid] = 0; }
        __syncthreads();
    }

    int v = (blockIdx.x * blockDim.x + tid) >> 5;
    int lane = tid & 31;
    bool active = (v < N_NODES);
    float4 o = make_float4(0.f, 0.f, 0.f, 0.f);

    if (active) {
        const uint2* T = (const uint2*)g_tb;
        uint2 sv = T[v * 32 + lane];
        float a0 = bf_lo(sv.x), a1 = bf_hi(sv.x), a2 = bf_lo(sv.y), a3 = bf_hi(sv.y);

        int i = g_off[v], e = g_off[v + 1];
        for (; i + 4 <= e; i += 4) {
            int r0 = __ldg(&g_csr[i]);
            int r1 = __ldg(&g_csr[i + 1]);
            int r2 = __ldg(&g_csr[i + 2]);
            int r3 = __ldg(&g_csr[i + 3]);
            uint2 m0 = T[r0 * 32 + lane];
            uint2 m1 = T[r1 * 32 + lane];
            uint2 m2 = T[r2 * 32 + lane];
            uint2 m3 = T[r3 * 32 + lane];
            a0 += (bf_lo(m0.x) + bf_lo(m1.x)) + (bf_lo(m2.x) + bf_lo(m3.x));
            a1 += (bf_hi(m0.x) + bf_hi(m1.x)) + (bf_hi(m2.x) + bf_hi(m3.x));
            a2 += (bf_lo(m0.y) + bf_lo(m1.y)) + (bf_lo(m2.y) + bf_lo(m3.y));
            a3 += (bf_hi(m0.y) + bf_hi(m1.y)) + (bf_hi(m2.y) + bf_hi(m3.y));
        }
        for (; i < e; i++) {
            int r = __ldg(&g_csr[i]);
            uint2 m = T[r * 32 + lane];
            a0 += bf_lo(m.x); a1 += bf_hi(m.x); a2 += bf_lo(m.y); a3 += bf_hi(m.y);
        }

        float dv = g_dis[v];
        float4 hv = *(const float4*)(g_h + v * HID + lane * 4);
        float4 bv = ((const float4*)b)[lane];
        float x0 = hv.x + fmaxf(dv * a0 + bv.x, 0.f);
        float x1 = hv.y + fmaxf(dv * a1 + bv.y, 0.f);
        float x2 = hv.z + fmaxf(dv * a2 + bv.z, 0.f);
        float x3 = hv.w + fmaxf(dv * a3 + bv.w, 0.f);

        float s = x0 + x1 + x2 + x3;
        #pragma unroll
        for (int off = 16; off > 0; off >>= 1) s += __shfl_xor_sync(0xffffffffu, s, off);
        float mu = s * (1.f / 128.f);
        float d0 = x0 - mu, d1 = x1 - mu, d2 = x2 - mu, d3 = x3 - mu;
        float q = d0 * d0 + d1 * d1 + d2 * d2 + d3 * d3;
        #pragma unroll
        for (int off = 16; off > 0; off >>= 1) q += __shfl_xor_sync(0xffffffffu, q, off);
        float rs = rsqrtf(q * (1.f / 128.f) + LN_EPS);
        float4 gv = ((const float4*)gamma)[lane];
        float4 be = ((const float4*)beta)[lane];
        o.x = d0 * rs * gv.x + be.x;
        o.y = d1 * rs * gv.y + be.y;
        o.z = d2 * rs * gv.z + be.z;
        o.w = d3 * rs * gv.w + be.w;
        *(float4*)(g_h + v * HID + lane * 4) = o;
    }

    if (pool) {
        float s = 0.f;
        if (active) {
            float4 wv = ((const float4*)Wout)[lane];
            s = o.x * wv.x + o.y * wv.y + o.z * wv.z + o.w * wv.w;
        }
        #pragma unroll
        for (int off = 16; off > 0; off >>= 1) s += __shfl_xor_sync(0xffffffffu, s, off);
        if (active && lane == 0) {
            int bg = g_batch[v];
            atomicAdd(&ssum[bg], s);
            atomicAdd(&scnt[bg], 1);
        }
        __syncthreads();
        if (tid < N_GRAPHS && scnt[tid] > 0) {
            atomicAdd(&g_sums[tid], ssum[tid]);
            atomicAdd(&g_cnts[tid], scnt[tid]);
        }
    }
}

// ---- output + state re-zero ----
__global__ void __launch_bounds__(256) k_out(float* out) {
    int i = blockIdx.x * 256 + threadIdx.x;
    if (blockIdx.x == 0 && threadIdx.x < N_GRAPHS) {
        int g = threadIdx.x;
        out[g] = g_sums[g] / fmaxf((float)g_cnts[g], 1.f);
        g_sums[g] = 0.f;
        g_cnts[g] = 0;
    }
    if (i < N_NODES) g_edeg[i] = 0;
}

// ---------------- launch ----------------
extern "C" void kernel_launch(void* const* d_in, const int* in_sizes, int n_in,
                              void* d_out, int out_size) {
    const float* x        = (const float*)d_in[0];
    const void*  ei       = d_in[1];
    const void*  batch    = d_in[2];
    const float* W_emb    = (const float*)d_in[3];
    const float* b_emb    = (const float*)d_in[4];
    const float* W_layers = (const float*)d_in[5];
    const float* b_layers = (const float*)d_in[6];
    const float* ln_gamma = (const float*)d_in[7];
    const float* ln_beta  = (const float*)d_in[8];
    const float* W_out    = (const float*)d_in[9];
    float* out = (float*)d_out;

    const int MMA_SMEM = 3 * 128 * SKW * sizeof(u32);   // 104,448 B -> 2 CTAs/SM
    static cudaStream_t s2 = nullptr;
    static cudaEvent_t evA = nullptr, evB = nullptr;
    if (!s2) {
        cudaFuncSetAttribute(k_mma, cudaFuncAttributeMaxDynamicSharedMemorySize, MMA_SMEM);
        cudaStreamCreateWithFlags(&s2, cudaStreamNonBlocking);
        cudaEventCreateWithFlags(&evA, cudaEventDisableTiming);
        cudaEventCreateWithFlags(&evB, cudaEventDisableTiming);
    }

    float* d_h = nullptr;
    cudaGetSymbolAddress((void**)&d_h, g_h);
    u32* whi = nullptr;
    cudaGetSymbolAddress((void**)&whi, g_Whi);
    u32* wlo = nullptr;
    cudaGetSymbolAddress((void**)&wlo, g_Wlo);

    // fork: side stream does W prep + embedding GEMM (independent of graph preamble)
    cudaEventRecord(evA, 0);
    cudaStreamWaitEvent(s2, evA, 0);
    k_wprep<<<WPBLK, 256, 0, s2>>>(W_emb, W_layers);
    k_mma<<<MMA_BLOCKS, 256, MMA_SMEM, s2>>>(x, whi, wlo, b_emb, 0);
    cudaEventRecord(evB, s2);

    // main stream: graph preamble
    k_convert<<<EBLK, 256>>>(ei, batch);
    k_blocksum<<<NBLK, 256>>>();
    k_offsets<<<NBLK, 256>>>();
    k_fill<<<EBLK, 256>>>();

    // join
    cudaStreamWaitEvent(0, evB, 0);

    int gln_blocks = (N_NODES + 15) / 16;    // 3125
    for (int i = 0; i < 4; i++) {
        k_mma<<<MMA_BLOCKS, 256, MMA_SMEM>>>(d_h, whi + (1 + i) * 8192, wlo + (1 + i) * 8192,
                                             nullptr, 1);
        k_gln<<<gln_blocks, 512>>>(b_layers + i * HID, ln_gamma + i * HID, ln_beta + i * HID,
                                   (i == 3) ? W_out : nullptr);
    }

    k_out<<<NBLK, 256>>>(out);
}